// round 1
// baseline (speedup 1.0000x reference)
#include <cuda_runtime.h>
#include <cstdint>

#define DMODEL 1024
#define NHEAD 16
#define DKH 64
#define BATCH 4
#define SEQ 2048
#define MTOT (BATCH*SEQ)   // 8192

// ---------------- scratch (static device globals; no allocation) ----------
__device__ float g_Q[BATCH*SEQ*DMODEL];
__device__ float g_K[BATCH*SEQ*DMODEL];
__device__ float g_V[BATCH*SEQ*DMODEL];
__device__ float g_AO[BATCH*SEQ*DMODEL];

// ---------------- packed f32x2 helpers ------------------------------------
__device__ __forceinline__ unsigned long long pack2(float x) {
    unsigned long long r;
    asm("mov.b64 %0, {%1, %1};" : "=l"(r) : "f"(x));
    return r;
}
__device__ __forceinline__ unsigned long long fma2(unsigned long long a,
                                                   unsigned long long b,
                                                   unsigned long long c) {
    unsigned long long d;
    asm("fma.rn.f32x2 %0, %1, %2, %3;" : "=l"(d) : "l"(a), "l"(b), "l"(c));
    return d;
}

// ---------------- SGEMM: C[M,N] = A[M,K] @ B[K,N], fp32, f32x2 inner ------
#define BM 128
#define BN 128
#define BKK 16
#define SAS 132
#define SBS 132

__global__ __launch_bounds__(256) void sgemm_kernel(
        const float* __restrict__ A, const float* __restrict__ B,
        float* __restrict__ C, int M, int N, int K)
{
    __shared__ float As[BKK*SAS];   // transposed: As[k][m]
    __shared__ float Bs[BKK*SBS];   // Bs[k][n]
    const int tid = threadIdx.x;
    const int ty = tid >> 4;        // 0..15
    const int tx = tid & 15;        // 0..15
    const int bm = blockIdx.y * BM;
    const int bn = blockIdx.x * BN;

    unsigned long long acc[2][2][4][2];
    #pragma unroll
    for (int si = 0; si < 2; si++)
        #pragma unroll
        for (int sj = 0; sj < 2; sj++)
            #pragma unroll
            for (int i = 0; i < 4; i++) {
                acc[si][sj][i][0] = 0ULL;
                acc[si][sj][i][1] = 0ULL;
            }

    for (int kt = 0; kt < K; kt += BKK) {
        // A tile 128x16 -> transposed into As[k][m]
        #pragma unroll
        for (int t = 0; t < 2; t++) {
            int i  = tid + t * 256;
            int ar = i >> 2;            // 0..127
            int ac = (i & 3) << 2;      // 0,4,8,12
            const float4 v = *(const float4*)(A + (size_t)(bm + ar) * K + kt + ac);
            As[(ac + 0) * SAS + ar] = v.x;
            As[(ac + 1) * SAS + ar] = v.y;
            As[(ac + 2) * SAS + ar] = v.z;
            As[(ac + 3) * SAS + ar] = v.w;
        }
        // B tile 16x128
        #pragma unroll
        for (int t = 0; t < 2; t++) {
            int i  = tid + t * 256;
            int br = i >> 5;            // 0..15
            int bc = (i & 31) << 2;     // 0..124
            *(float4*)(Bs + br * SBS + bc) =
                *(const float4*)(B + (size_t)(kt + br) * N + bn + bc);
        }
        __syncthreads();

        #pragma unroll
        for (int k = 0; k < BKK; k++) {
            float a[2][4];
            union { float4 f; unsigned long long u[2]; } b0, b1;
            *(float4*)a[0] = *(const float4*)(As + k * SAS + ty * 4);
            *(float4*)a[1] = *(const float4*)(As + k * SAS + 64 + ty * 4);
            b0.f = *(const float4*)(Bs + k * SBS + tx * 4);
            b1.f = *(const float4*)(Bs + k * SBS + 64 + tx * 4);
            #pragma unroll
            for (int si = 0; si < 2; si++) {
                #pragma unroll
                for (int i = 0; i < 4; i++) {
                    unsigned long long av = pack2(a[si][i]);
                    acc[si][0][i][0] = fma2(av, b0.u[0], acc[si][0][i][0]);
                    acc[si][0][i][1] = fma2(av, b0.u[1], acc[si][0][i][1]);
                    acc[si][1][i][0] = fma2(av, b1.u[0], acc[si][1][i][0]);
                    acc[si][1][i][1] = fma2(av, b1.u[1], acc[si][1][i][1]);
                }
            }
        }
        __syncthreads();
    }

    #pragma unroll
    for (int si = 0; si < 2; si++)
        #pragma unroll
        for (int i = 0; i < 4; i++)
            #pragma unroll
            for (int sj = 0; sj < 2; sj++) {
                union { float4 f; unsigned long long u[2]; } o;
                o.u[0] = acc[si][sj][i][0];
                o.u[1] = acc[si][sj][i][1];
                *(float4*)(C + (size_t)(bm + si * 64 + ty * 4 + i) * N
                             + bn + sj * 64 + tx * 4) = o.f;
            }
}

// ---------------- flash attention: one CTA per (b, h, 64-query tile) ------
#define APAD 65
#define ATTN_SMEM ((4 * 64 * APAD + 64) * (int)sizeof(float))

__global__ __launch_bounds__(256) void attn_kernel(
        const float* __restrict__ Q, const float* __restrict__ K,
        const float* __restrict__ V, const int* __restrict__ mask,
        float* __restrict__ O)
{
    extern __shared__ float sm[];
    float* Qs = sm;                 // [64][APAD]
    float* Ks = Qs + 64 * APAD;     // [64][APAD]
    float* Vs = Ks + 64 * APAD;     // [64][APAD]
    float* Ps = Vs + 64 * APAD;     // [64][APAD]  exp'd probabilities
    float* mk = Ps + 64 * APAD;     // [64] additive mask

    const int tid = threadIdx.x;
    const int ty = tid >> 4;        // row group 0..15 (rows ty*4..ty*4+3)
    const int tx = tid & 15;        // col/dim group  (cols tx*4..tx*4+3)
    const int qt = blockIdx.x;
    const int h  = blockIdx.y;
    const int b  = blockIdx.z;

    const size_t qrow0 = (size_t)b * SEQ + (size_t)qt * 64;
    const float* Qg = Q + qrow0 * DMODEL + h * DKH;

    // load Q tile 64x64
    #pragma unroll
    for (int t = 0; t < 4; t++) {
        int i  = tid + t * 256;
        int r  = i >> 4;
        int d4 = (i & 15) << 2;
        float4 v = *(const float4*)(Qg + (size_t)r * DMODEL + d4);
        Qs[r * APAD + d4 + 0] = v.x;
        Qs[r * APAD + d4 + 1] = v.y;
        Qs[r * APAD + d4 + 2] = v.z;
        Qs[r * APAD + d4 + 3] = v.w;
    }

    float mstate[4], lstate[4], o[4][4];
    #pragma unroll
    for (int i = 0; i < 4; i++) {
        mstate[i] = -1e30f;
        lstate[i] = 0.0f;
        #pragma unroll
        for (int j = 0; j < 4; j++) o[i][j] = 0.0f;
    }
    __syncthreads();

    for (int kt = 0; kt < SEQ / 64; kt++) {
        if (kt) __syncthreads();    // WAR on Ks/Vs/Ps/mk
        const size_t krow0 = (size_t)b * SEQ + (size_t)kt * 64;
        const float* Kg = K + krow0 * DMODEL + h * DKH;
        const float* Vg = V + krow0 * DMODEL + h * DKH;
        #pragma unroll
        for (int t = 0; t < 4; t++) {
            int i  = tid + t * 256;
            int r  = i >> 4;
            int d4 = (i & 15) << 2;
            float4 kv = *(const float4*)(Kg + (size_t)r * DMODEL + d4);
            Ks[r * APAD + d4 + 0] = kv.x;
            Ks[r * APAD + d4 + 1] = kv.y;
            Ks[r * APAD + d4 + 2] = kv.z;
            Ks[r * APAD + d4 + 3] = kv.w;
            float4 vv = *(const float4*)(Vg + (size_t)r * DMODEL + d4);
            Vs[r * APAD + d4 + 0] = vv.x;
            Vs[r * APAD + d4 + 1] = vv.y;
            Vs[r * APAD + d4 + 2] = vv.z;
            Vs[r * APAD + d4 + 3] = vv.w;
        }
        if (tid < 64)
            mk[tid] = (1.0f - (float)mask[krow0 + tid]) * -1e9f;
        __syncthreads();

        // ---- scores: S = Q K^T (4x4 per thread) ----
        float s[4][4];
        #pragma unroll
        for (int i = 0; i < 4; i++)
            #pragma unroll
            for (int j = 0; j < 4; j++) s[i][j] = 0.0f;

        #pragma unroll 16
        for (int d = 0; d < 64; d++) {
            float q0 = Qs[(ty * 4 + 0) * APAD + d];
            float q1 = Qs[(ty * 4 + 1) * APAD + d];
            float q2 = Qs[(ty * 4 + 2) * APAD + d];
            float q3 = Qs[(ty * 4 + 3) * APAD + d];
            float k0 = Ks[(tx * 4 + 0) * APAD + d];
            float k1 = Ks[(tx * 4 + 1) * APAD + d];
            float k2 = Ks[(tx * 4 + 2) * APAD + d];
            float k3 = Ks[(tx * 4 + 3) * APAD + d];
            s[0][0] += q0 * k0; s[0][1] += q0 * k1; s[0][2] += q0 * k2; s[0][3] += q0 * k3;
            s[1][0] += q1 * k0; s[1][1] += q1 * k1; s[1][2] += q1 * k2; s[1][3] += q1 * k3;
            s[2][0] += q2 * k0; s[2][1] += q2 * k1; s[2][2] += q2 * k2; s[2][3] += q2 * k3;
            s[3][0] += q3 * k0; s[3][1] += q3 * k1; s[3][2] += q3 * k2; s[3][3] += q3 * k3;
        }

        // ---- online softmax (rows owned by this ty group; reduce over tx) ----
        #pragma unroll
        for (int i = 0; i < 4; i++) {
            float rmax = -1e30f;
            #pragma unroll
            for (int j = 0; j < 4; j++) {
                s[i][j] = s[i][j] * 0.125f + mk[tx * 4 + j];
                rmax = fmaxf(rmax, s[i][j]);
            }
            rmax = fmaxf(rmax, __shfl_xor_sync(0xffffffffu, rmax, 1));
            rmax = fmaxf(rmax, __shfl_xor_sync(0xffffffffu, rmax, 2));
            rmax = fmaxf(rmax, __shfl_xor_sync(0xffffffffu, rmax, 4));
            rmax = fmaxf(rmax, __shfl_xor_sync(0xffffffffu, rmax, 8));
            float newm  = fmaxf(mstate[i], rmax);
            float alpha = __expf(mstate[i] - newm);
            mstate[i] = newm;
            float rs = 0.0f;
            #pragma unroll
            for (int j = 0; j < 4; j++) {
                float p = __expf(s[i][j] - newm);
                Ps[(ty * 4 + i) * APAD + tx * 4 + j] = p;
                rs += p;
            }
            rs += __shfl_xor_sync(0xffffffffu, rs, 1);
            rs += __shfl_xor_sync(0xffffffffu, rs, 2);
            rs += __shfl_xor_sync(0xffffffffu, rs, 4);
            rs += __shfl_xor_sync(0xffffffffu, rs, 8);
            lstate[i] = lstate[i] * alpha + rs;
            #pragma unroll
            for (int j = 0; j < 4; j++) o[i][j] *= alpha;
        }
        __syncwarp();   // Ps producers/consumers for a row group share a warp

        // ---- O += P V ----
        #pragma unroll 16
        for (int c = 0; c < 64; c++) {
            float p0 = Ps[(ty * 4 + 0) * APAD + c];
            float p1 = Ps[(ty * 4 + 1) * APAD + c];
            float p2 = Ps[(ty * 4 + 2) * APAD + c];
            float p3 = Ps[(ty * 4 + 3) * APAD + c];
            float v0 = Vs[c * APAD + tx * 4 + 0];
            float v1 = Vs[c * APAD + tx * 4 + 1];
            float v2 = Vs[c * APAD + tx * 4 + 2];
            float v3 = Vs[c * APAD + tx * 4 + 3];
            o[0][0] += p0 * v0; o[0][1] += p0 * v1; o[0][2] += p0 * v2; o[0][3] += p0 * v3;
            o[1][0] += p1 * v0; o[1][1] += p1 * v1; o[1][2] += p1 * v2; o[1][3] += p1 * v3;
            o[2][0] += p2 * v0; o[2][1] += p2 * v1; o[2][2] += p2 * v2; o[2][3] += p2 * v3;
            o[3][0] += p3 * v0; o[3][1] += p3 * v1; o[3][2] += p3 * v2; o[3][3] += p3 * v3;
        }
    }

    float* Og = O + qrow0 * DMODEL + h * DKH;
    #pragma unroll
    for (int i = 0; i < 4; i++) {
        float inv = 1.0f / lstate[i];
        float4 v = make_float4(o[i][0] * inv, o[i][1] * inv,
                               o[i][2] * inv, o[i][3] * inv);
        *(float4*)(Og + (size_t)(ty * 4 + i) * DMODEL + tx * 4) = v;
    }
}

// ---------------- launch ---------------------------------------------------
extern "C" void kernel_launch(void* const* d_in, const int* in_sizes, int n_in,
                              void* d_out, int out_size) {
    const float* X    = (const float*)d_in[0];
    const int*   mask = (const int*)d_in[1];
    const float* Wq   = (const float*)d_in[2];
    const float* Wk   = (const float*)d_in[3];
    const float* Wv   = (const float*)d_in[4];
    const float* Wo   = (const float*)d_in[5];
    float* out = (float*)d_out;

    float *q, *k, *v, *ao;
    cudaGetSymbolAddress((void**)&q,  g_Q);
    cudaGetSymbolAddress((void**)&k,  g_K);
    cudaGetSymbolAddress((void**)&v,  g_V);
    cudaGetSymbolAddress((void**)&ao, g_AO);

    cudaFuncSetAttribute(attn_kernel,
                         cudaFuncAttributeMaxDynamicSharedMemorySize, ATTN_SMEM);

    dim3 gg(DMODEL / BN, MTOT / BM);   // (8, 64)
    sgemm_kernel<<<gg, 256>>>(X, Wq, q, MTOT, DMODEL, DMODEL);
    sgemm_kernel<<<gg, 256>>>(X, Wk, k, MTOT, DMODEL, DMODEL);
    sgemm_kernel<<<gg, 256>>>(X, Wv, v, MTOT, DMODEL, DMODEL);

    attn_kernel<<<dim3(SEQ / 64, NHEAD, BATCH), 256, ATTN_SMEM>>>(q, k, v, mask, ao);

    sgemm_kernel<<<gg, 256>>>(ao, Wo, out, MTOT, DMODEL, DMODEL);
}

// round 3
// speedup vs baseline: 1.3480x; 1.3480x over previous
#include <cuda_runtime.h>
#include <cstdint>

#define DMODEL 1024
#define NHEAD 16
#define DKH 64
#define BATCH 4
#define SEQ 2048
#define MTOT (BATCH*SEQ)   // 8192

// ---------------- scratch (static device globals; no allocation) ----------
__device__ float g_Q[BATCH*SEQ*DMODEL];
__device__ float g_K[BATCH*SEQ*DMODEL];
__device__ float g_V[BATCH*SEQ*DMODEL];
__device__ float g_AO[BATCH*SEQ*DMODEL];
__device__ float g_WT[4*DMODEL*DMODEL];   // transposed weights [N,K]

// ---------------- helpers ---------------------------------------------------
__device__ __forceinline__ uint32_t smem_u32(const void* p) {
    uint32_t a;
    asm("{ .reg .u64 t; cvta.to.shared.u64 t, %1; cvt.u32.u64 %0, t; }"
        : "=r"(a) : "l"(p));
    return a;
}
__device__ __forceinline__ void cp16(uint32_t smem_addr, const void* gptr) {
    asm volatile("cp.async.cg.shared.global [%0], [%1], 16;"
                 :: "r"(smem_addr), "l"(gptr));
}
#define CP_COMMIT() asm volatile("cp.async.commit_group;" ::: "memory")

__device__ __forceinline__ uint32_t f2tf32(float x) {
    uint32_t r;
    asm("cvt.rna.tf32.f32 %0, %1;" : "=r"(r) : "f"(x));
    return r;
}
__device__ __forceinline__ void mma_tf32(float* c, const uint32_t* a,
                                         const uint32_t* b) {
    asm volatile(
        "mma.sync.aligned.m16n8k8.row.col.f32.tf32.tf32.f32 "
        "{%0,%1,%2,%3}, {%4,%5,%6,%7}, {%8,%9}, {%0,%1,%2,%3};"
        : "+f"(c[0]), "+f"(c[1]), "+f"(c[2]), "+f"(c[3])
        : "r"(a[0]), "r"(a[1]), "r"(a[2]), "r"(a[3]), "r"(b[0]), "r"(b[1]));
}

// ---------------- transpose [K,N] -> [N,K] ---------------------------------
__global__ __launch_bounds__(256) void transpose_kernel(
        const float* __restrict__ in, float* __restrict__ out)
{
    __shared__ float t[32][33];
    int x = blockIdx.x * 32 + threadIdx.x;
    int y = blockIdx.y * 32 + threadIdx.y;
    #pragma unroll
    for (int j = 0; j < 32; j += 8)
        t[threadIdx.y + j][threadIdx.x] = in[(size_t)(y + j) * DMODEL + x];
    __syncthreads();
    x = blockIdx.y * 32 + threadIdx.x;
    y = blockIdx.x * 32 + threadIdx.y;
    #pragma unroll
    for (int j = 0; j < 32; j += 8)
        out[(size_t)(y + j) * DMODEL + x] = t[threadIdx.x][threadIdx.y + j];
}

// ---------------- tf32 mma.sync GEMM: C[M,N] = A[M,K] @ Bt[N,K]^T ---------
// CTA 128x128, 8 warps of 64x32, k-tile 32, double-buffered cp.async.
#define NKT (DMODEL/32)          // 32 k-tiles
#define TSTR 36                  // padded row stride (floats): conflict-free frags
#define STAGEF (2*128*TSTR)      // floats per stage (A tile + B tile)
#define TGEMM_SMEM (2*STAGEF*(int)sizeof(float))   // 73728 B

__global__ __launch_bounds__(256) void tgemm_kernel(
        const float* __restrict__ A,   // [M, K] K-contig
        const float* __restrict__ Bt,  // [N, K] K-contig
        float* __restrict__ C, int M, int N, int K)
{
    extern __shared__ float sm[];
    const int tid  = threadIdx.x;
    const int wid  = tid >> 5;
    const int lane = tid & 31;
    const int bm = blockIdx.y * 128;
    const int bn = blockIdx.x * 128;
    const int wm = (wid & 1) * 64;    // warp row offset in tile
    const int wn = (wid >> 1) * 32;   // warp col offset in tile

    float acc[4][4][4];
    #pragma unroll
    for (int mt = 0; mt < 4; mt++)
        #pragma unroll
        for (int nt = 0; nt < 4; nt++)
            #pragma unroll
            for (int i = 0; i < 4; i++) acc[mt][nt][i] = 0.0f;

    const float* gA = A  + (size_t)bm * K;
    const float* gB = Bt + (size_t)bn * K;

    // load A+B k-tile kt into stage s; 8 cp16 per thread (4 A + 4 B)
    auto load_stage = [&](int s, int kt) {
        uint32_t base = smem_u32(sm + s * STAGEF);
        uint32_t baseB = base + 128 * TSTR * 4;
        const float* pa = gA + kt * 32;
        const float* pb = gB + kt * 32;
        #pragma unroll
        for (int i = 0; i < 4; i++) {
            int idx = tid + i * 256;          // 0..1023
            int r = idx >> 3;                 // 0..127
            int c = idx & 7;                  // 16B chunk
            uint32_t off = (uint32_t)(r * TSTR * 4 + c * 16);
            cp16(base  + off, pa + (size_t)r * K + c * 4);
            cp16(baseB + off, pb + (size_t)r * K + c * 4);
        }
        CP_COMMIT();
    };

    load_stage(0, 0);
    load_stage(1, 1);

    const int lr = lane >> 2;   // 0..7
    const int lc = lane & 3;    // 0..3

    for (int kt = 0; kt < NKT; kt++) {
        int s = kt & 1;
        if (kt < NKT - 1) asm volatile("cp.async.wait_group 1;" ::: "memory");
        else              asm volatile("cp.async.wait_group 0;" ::: "memory");
        __syncthreads();

        const float* As = sm + s * STAGEF;
        const float* Bs = As + 128 * TSTR;

        #pragma unroll
        for (int ks = 0; ks < 4; ks++) {
            int k0 = ks * 8;
            uint32_t bf[4][2];
            #pragma unroll
            for (int nt = 0; nt < 4; nt++) {
                int col = wn + nt * 8 + lr;
                bf[nt][0] = f2tf32(Bs[col * TSTR + k0 + lc]);
                bf[nt][1] = f2tf32(Bs[col * TSTR + k0 + lc + 4]);
            }
            #pragma unroll
            for (int mt = 0; mt < 4; mt++) {
                int row = wm + mt * 16 + lr;
                uint32_t af[4];
                af[0] = f2tf32(As[row * TSTR + k0 + lc]);
                af[1] = f2tf32(As[(row + 8) * TSTR + k0 + lc]);
                af[2] = f2tf32(As[row * TSTR + k0 + lc + 4]);
                af[3] = f2tf32(As[(row + 8) * TSTR + k0 + lc + 4]);
                #pragma unroll
                for (int nt = 0; nt < 4; nt++)
                    mma_tf32(acc[mt][nt], af, bf[nt]);
            }
        }
        __syncthreads();
        if (kt + 2 < NKT) load_stage(s, kt + 2);
    }

    // epilogue: c0,c1 at (row, 2*lc), c2,c3 at (row+8, 2*lc)
    #pragma unroll
    for (int mt = 0; mt < 4; mt++) {
        int row = bm + wm + mt * 16 + lr;
        #pragma unroll
        for (int nt = 0; nt < 4; nt++) {
            int col = bn + wn + nt * 8 + 2 * lc;
            *(float2*)(C + (size_t)row * N + col) =
                make_float2(acc[mt][nt][0], acc[mt][nt][1]);
            *(float2*)(C + (size_t)(row + 8) * N + col) =
                make_float2(acc[mt][nt][2], acc[mt][nt][3]);
        }
    }
}

// ---------------- flash attention: one CTA per (b, h, 64-query tile) ------
#define APAD 65
#define ATTN_SMEM ((4 * 64 * APAD + 64) * (int)sizeof(float))

__global__ __launch_bounds__(256) void attn_kernel(
        const float* __restrict__ Q, const float* __restrict__ K,
        const float* __restrict__ V, const int* __restrict__ mask,
        float* __restrict__ O)
{
    extern __shared__ float sm[];
    float* Qs = sm;                 // [64][APAD]
    float* Ks = Qs + 64 * APAD;
    float* Vs = Ks + 64 * APAD;
    float* Ps = Vs + 64 * APAD;
    float* mk = Ps + 64 * APAD;     // [64]

    const int tid = threadIdx.x;
    const int ty = tid >> 4;
    const int tx = tid & 15;
    const int qt = blockIdx.x;
    const int h  = blockIdx.y;
    const int b  = blockIdx.z;

    const size_t qrow0 = (size_t)b * SEQ + (size_t)qt * 64;
    const float* Qg = Q + qrow0 * DMODEL + h * DKH;

    #pragma unroll
    for (int t = 0; t < 4; t++) {
        int i  = tid + t * 256;
        int r  = i >> 4;
        int d4 = (i & 15) << 2;
        float4 v = *(const float4*)(Qg + (size_t)r * DMODEL + d4);
        Qs[r * APAD + d4 + 0] = v.x;
        Qs[r * APAD + d4 + 1] = v.y;
        Qs[r * APAD + d4 + 2] = v.z;
        Qs[r * APAD + d4 + 3] = v.w;
    }

    float mstate[4], lstate[4], o[4][4];
    #pragma unroll
    for (int i = 0; i < 4; i++) {
        mstate[i] = -1e30f;
        lstate[i] = 0.0f;
        #pragma unroll
        for (int j = 0; j < 4; j++) o[i][j] = 0.0f;
    }
    __syncthreads();

    for (int kt = 0; kt < SEQ / 64; kt++) {
        if (kt) __syncthreads();
        const size_t krow0 = (size_t)b * SEQ + (size_t)kt * 64;
        const float* Kg = K + krow0 * DMODEL + h * DKH;
        const float* Vg = V + krow0 * DMODEL + h * DKH;
        #pragma unroll
        for (int t = 0; t < 4; t++) {
            int i  = tid + t * 256;
            int r  = i >> 4;
            int d4 = (i & 15) << 2;
            float4 kv = *(const float4*)(Kg + (size_t)r * DMODEL + d4);
            Ks[r * APAD + d4 + 0] = kv.x;
            Ks[r * APAD + d4 + 1] = kv.y;
            Ks[r * APAD + d4 + 2] = kv.z;
            Ks[r * APAD + d4 + 3] = kv.w;
            float4 vv = *(const float4*)(Vg + (size_t)r * DMODEL + d4);
            Vs[r * APAD + d4 + 0] = vv.x;
            Vs[r * APAD + d4 + 1] = vv.y;
            Vs[r * APAD + d4 + 2] = vv.z;
            Vs[r * APAD + d4 + 3] = vv.w;
        }
        if (tid < 64)
            mk[tid] = (1.0f - (float)mask[krow0 + tid]) * -1e9f;
        __syncthreads();

        float s[4][4];
        #pragma unroll
        for (int i = 0; i < 4; i++)
            #pragma unroll
            for (int j = 0; j < 4; j++) s[i][j] = 0.0f;

        #pragma unroll 16
        for (int d = 0; d < 64; d++) {
            float q0 = Qs[(ty * 4 + 0) * APAD + d];
            float q1 = Qs[(ty * 4 + 1) * APAD + d];
            float q2 = Qs[(ty * 4 + 2) * APAD + d];
            float q3 = Qs[(ty * 4 + 3) * APAD + d];
            float k0 = Ks[(tx * 4 + 0) * APAD + d];
            float k1 = Ks[(tx * 4 + 1) * APAD + d];
            float k2 = Ks[(tx * 4 + 2) * APAD + d];
            float k3 = Ks[(tx * 4 + 3) * APAD + d];
            s[0][0] += q0 * k0; s[0][1] += q0 * k1; s[0][2] += q0 * k2; s[0][3] += q0 * k3;
            s[1][0] += q1 * k0; s[1][1] += q1 * k1; s[1][2] += q1 * k2; s[1][3] += q1 * k3;
            s[2][0] += q2 * k0; s[2][1] += q2 * k1; s[2][2] += q2 * k2; s[2][3] += q2 * k3;
            s[3][0] += q3 * k0; s[3][1] += q3 * k1; s[3][2] += q3 * k2; s[3][3] += q3 * k3;
        }

        #pragma unroll
        for (int i = 0; i < 4; i++) {
            float rmax = -1e30f;
            #pragma unroll
            for (int j = 0; j < 4; j++) {
                s[i][j] = s[i][j] * 0.125f + mk[tx * 4 + j];
                rmax = fmaxf(rmax, s[i][j]);
            }
            rmax = fmaxf(rmax, __shfl_xor_sync(0xffffffffu, rmax, 1));
            rmax = fmaxf(rmax, __shfl_xor_sync(0xffffffffu, rmax, 2));
            rmax = fmaxf(rmax, __shfl_xor_sync(0xffffffffu, rmax, 4));
            rmax = fmaxf(rmax, __shfl_xor_sync(0xffffffffu, rmax, 8));
            float newm  = fmaxf(mstate[i], rmax);
            float alpha = __expf(mstate[i] - newm);
            mstate[i] = newm;
            float rs = 0.0f;
            #pragma unroll
            for (int j = 0; j < 4; j++) {
                float p = __expf(s[i][j] - newm);
                Ps[(ty * 4 + i) * APAD + tx * 4 + j] = p;
                rs += p;
            }
            rs += __shfl_xor_sync(0xffffffffu, rs, 1);
            rs += __shfl_xor_sync(0xffffffffu, rs, 2);
            rs += __shfl_xor_sync(0xffffffffu, rs, 4);
            rs += __shfl_xor_sync(0xffffffffu, rs, 8);
            lstate[i] = lstate[i] * alpha + rs;
            #pragma unroll
            for (int j = 0; j < 4; j++) o[i][j] *= alpha;
        }
        __syncwarp();

        #pragma unroll 16
        for (int c = 0; c < 64; c++) {
            float p0 = Ps[(ty * 4 + 0) * APAD + c];
            float p1 = Ps[(ty * 4 + 1) * APAD + c];
            float p2 = Ps[(ty * 4 + 2) * APAD + c];
            float p3 = Ps[(ty * 4 + 3) * APAD + c];
            float v0 = Vs[c * APAD + tx * 4 + 0];
            float v1 = Vs[c * APAD + tx * 4 + 1];
            float v2 = Vs[c * APAD + tx * 4 + 2];
            float v3 = Vs[c * APAD + tx * 4 + 3];
            o[0][0] += p0 * v0; o[0][1] += p0 * v1; o[0][2] += p0 * v2; o[0][3] += p0 * v3;
            o[1][0] += p1 * v0; o[1][1] += p1 * v1; o[1][2] += p1 * v2; o[1][3] += p1 * v3;
            o[2][0] += p2 * v0; o[2][1] += p2 * v1; o[2][2] += p2 * v2; o[2][3] += p2 * v3;
            o[3][0] += p3 * v0; o[3][1] += p3 * v1; o[3][2] += p3 * v2; o[3][3] += p3 * v3;
        }
    }

    float* Og = O + qrow0 * DMODEL + h * DKH;
    #pragma unroll
    for (int i = 0; i < 4; i++) {
        float inv = 1.0f / lstate[i];
        float4 v = make_float4(o[i][0] * inv, o[i][1] * inv,
                               o[i][2] * inv, o[i][3] * inv);
        *(float4*)(Og + (size_t)(ty * 4 + i) * DMODEL + tx * 4) = v;
    }
}

// ---------------- launch ---------------------------------------------------
extern "C" void kernel_launch(void* const* d_in, const int* in_sizes, int n_in,
                              void* d_out, int out_size) {
    const float* X    = (const float*)d_in[0];
    const int*   mask = (const int*)d_in[1];
    const float* Wq   = (const float*)d_in[2];
    const float* Wk   = (const float*)d_in[3];
    const float* Wv   = (const float*)d_in[4];
    const float* Wo   = (const float*)d_in[5];
    float* out = (float*)d_out;

    float *q, *k, *v, *ao, *wt;
    cudaGetSymbolAddress((void**)&q,  g_Q);
    cudaGetSymbolAddress((void**)&k,  g_K);
    cudaGetSymbolAddress((void**)&v,  g_V);
    cudaGetSymbolAddress((void**)&ao, g_AO);
    cudaGetSymbolAddress((void**)&wt, g_WT);

    cudaFuncSetAttribute(attn_kernel,
                         cudaFuncAttributeMaxDynamicSharedMemorySize, ATTN_SMEM);
    cudaFuncSetAttribute(tgemm_kernel,
                         cudaFuncAttributeMaxDynamicSharedMemorySize, TGEMM_SMEM);

    dim3 tgrid(32, 32), tblk(32, 8);
    transpose_kernel<<<tgrid, tblk>>>(Wq, wt + 0 * DMODEL * DMODEL);
    transpose_kernel<<<tgrid, tblk>>>(Wk, wt + 1 * DMODEL * DMODEL);
    transpose_kernel<<<tgrid, tblk>>>(Wv, wt + 2 * DMODEL * DMODEL);
    transpose_kernel<<<tgrid, tblk>>>(Wo, wt + 3 * DMODEL * DMODEL);

    dim3 gg(DMODEL / 128, MTOT / 128);   // (8, 64)
    tgemm_kernel<<<gg, 256, TGEMM_SMEM>>>(X, wt + 0 * DMODEL * DMODEL, q,  MTOT, DMODEL, DMODEL);
    tgemm_kernel<<<gg, 256, TGEMM_SMEM>>>(X, wt + 1 * DMODEL * DMODEL, k,  MTOT, DMODEL, DMODEL);
    tgemm_kernel<<<gg, 256, TGEMM_SMEM>>>(X, wt + 2 * DMODEL * DMODEL, v,  MTOT, DMODEL, DMODEL);

    attn_kernel<<<dim3(SEQ / 64, NHEAD, BATCH), 256, ATTN_SMEM>>>(q, k, v, mask, ao);

    tgemm_kernel<<<gg, 256, TGEMM_SMEM>>>(ao, wt + 3 * DMODEL * DMODEL, out, MTOT, DMODEL, DMODEL);
}

// round 5
// speedup vs baseline: 2.8647x; 2.1251x over previous
#include <cuda_runtime.h>
#include <cstdint>

#define DMODEL 1024
#define NHEAD 16
#define DKH 64
#define BATCH 4
#define SEQ 2048
#define MTOT (BATCH*SEQ)   // 8192

// ---------------- scratch (static device globals; no allocation) ----------
__device__ float g_Q[BATCH*SEQ*DMODEL];
__device__ float g_K[BATCH*SEQ*DMODEL];
__device__ float g_V[BATCH*SEQ*DMODEL];
__device__ float g_AO[BATCH*SEQ*DMODEL];
__device__ float g_WT[4*DMODEL*DMODEL];   // transposed weights [N,K]
__device__ float g_MF[BATCH*SEQ];         // additive float mask

// ---------------- helpers ---------------------------------------------------
__device__ __forceinline__ uint32_t smem_u32(const void* p) {
    uint32_t a;
    asm("{ .reg .u64 t; cvta.to.shared.u64 t, %1; cvt.u32.u64 %0, t; }"
        : "=r"(a) : "l"(p));
    return a;
}
__device__ __forceinline__ void cp16(uint32_t smem_addr, const void* gptr) {
    asm volatile("cp.async.cg.shared.global [%0], [%1], 16;"
                 :: "r"(smem_addr), "l"(gptr));
}
#define CP_COMMIT() asm volatile("cp.async.commit_group;" ::: "memory")

__device__ __forceinline__ uint32_t f2tf32(float x) {
    uint32_t r;
    asm("cvt.rna.tf32.f32 %0, %1;" : "=r"(r) : "f"(x));
    return r;
}
__device__ __forceinline__ void mma_tf32(float* c, const uint32_t* a,
                                         const uint32_t* b) {
    asm volatile(
        "mma.sync.aligned.m16n8k8.row.col.f32.tf32.tf32.f32 "
        "{%0,%1,%2,%3}, {%4,%5,%6,%7}, {%8,%9}, {%0,%1,%2,%3};"
        : "+f"(c[0]), "+f"(c[1]), "+f"(c[2]), "+f"(c[3])
        : "r"(a[0]), "r"(a[1]), "r"(a[2]), "r"(a[3]), "r"(b[0]), "r"(b[1]));
}

// ---------------- mask prep: int -> additive float -------------------------
__global__ void maskprep_kernel(const int* __restrict__ m, float* __restrict__ mf) {
    int i = blockIdx.x * 256 + threadIdx.x;
    if (i < BATCH * SEQ) mf[i] = (1.0f - (float)m[i]) * -1e9f;
}

// ---------------- transpose [K,N] -> [N,K] ---------------------------------
__global__ __launch_bounds__(256) void transpose_kernel(
        const float* __restrict__ in, float* __restrict__ out)
{
    __shared__ float t[32][33];
    int x = blockIdx.x * 32 + threadIdx.x;
    int y = blockIdx.y * 32 + threadIdx.y;
    #pragma unroll
    for (int j = 0; j < 32; j += 8)
        t[threadIdx.y + j][threadIdx.x] = in[(size_t)(y + j) * DMODEL + x];
    __syncthreads();
    x = blockIdx.y * 32 + threadIdx.x;
    y = blockIdx.x * 32 + threadIdx.y;
    #pragma unroll
    for (int j = 0; j < 32; j += 8)
        out[(size_t)(y + j) * DMODEL + x] = t[threadIdx.x][threadIdx.y + j];
}

// ---------------- tf32 mma.sync GEMM: C[M,N] = A[M,K] @ Bt[N,K]^T ---------
#define NKT (DMODEL/32)
#define TSTR 36
#define STAGEF (2*128*TSTR)
#define TGEMM_SMEM (2*STAGEF*(int)sizeof(float))

__global__ __launch_bounds__(256) void tgemm_kernel(
        const float* __restrict__ A, const float* __restrict__ Bt,
        float* __restrict__ C, int M, int N, int K)
{
    extern __shared__ float sm[];
    const int tid  = threadIdx.x;
    const int lane = tid & 31;
    const int wid  = tid >> 5;
    const int bm = blockIdx.y * 128;
    const int bn = blockIdx.x * 128;
    const int wm = (wid & 1) * 64;
    const int wn = (wid >> 1) * 32;

    float acc[4][4][4];
    #pragma unroll
    for (int mt = 0; mt < 4; mt++)
        #pragma unroll
        for (int nt = 0; nt < 4; nt++)
            #pragma unroll
            for (int i = 0; i < 4; i++) acc[mt][nt][i] = 0.0f;

    const float* gA = A  + (size_t)bm * K;
    const float* gB = Bt + (size_t)bn * K;

    auto load_stage = [&](int s, int kt) {
        uint32_t base = smem_u32(sm + s * STAGEF);
        uint32_t baseB = base + 128 * TSTR * 4;
        const float* pa = gA + kt * 32;
        const float* pb = gB + kt * 32;
        #pragma unroll
        for (int i = 0; i < 4; i++) {
            int idx = tid + i * 256;
            int r = idx >> 3;
            int c = idx & 7;
            uint32_t off = (uint32_t)(r * TSTR * 4 + c * 16);
            cp16(base  + off, pa + (size_t)r * K + c * 4);
            cp16(baseB + off, pb + (size_t)r * K + c * 4);
        }
        CP_COMMIT();
    };

    load_stage(0, 0);
    load_stage(1, 1);

    const int lr = lane >> 2;
    const int lc = lane & 3;

    for (int kt = 0; kt < NKT; kt++) {
        int s = kt & 1;
        if (kt < NKT - 1) asm volatile("cp.async.wait_group 1;" ::: "memory");
        else              asm volatile("cp.async.wait_group 0;" ::: "memory");
        __syncthreads();

        const float* As = sm + s * STAGEF;
        const float* Bs = As + 128 * TSTR;

        #pragma unroll
        for (int ks = 0; ks < 4; ks++) {
            int k0 = ks * 8;
            uint32_t bf[4][2];
            #pragma unroll
            for (int nt = 0; nt < 4; nt++) {
                int col = wn + nt * 8 + lr;
                bf[nt][0] = f2tf32(Bs[col * TSTR + k0 + lc]);
                bf[nt][1] = f2tf32(Bs[col * TSTR + k0 + lc + 4]);
            }
            #pragma unroll
            for (int mt = 0; mt < 4; mt++) {
                int row = wm + mt * 16 + lr;
                uint32_t af[4];
                af[0] = f2tf32(As[row * TSTR + k0 + lc]);
                af[1] = f2tf32(As[(row + 8) * TSTR + k0 + lc]);
                af[2] = f2tf32(As[row * TSTR + k0 + lc + 4]);
                af[3] = f2tf32(As[(row + 8) * TSTR + k0 + lc + 4]);
                #pragma unroll
                for (int nt = 0; nt < 4; nt++)
                    mma_tf32(acc[mt][nt], af, bf[nt]);
            }
        }
        __syncthreads();
        if (kt + 2 < NKT) load_stage(s, kt + 2);
    }

    #pragma unroll
    for (int mt = 0; mt < 4; mt++) {
        int row = bm + wm + mt * 16 + lr;
        #pragma unroll
        for (int nt = 0; nt < 4; nt++) {
            int col = bn + wn + nt * 8 + 2 * lc;
            *(float2*)(C + (size_t)row * N + col) =
                make_float2(acc[mt][nt][0], acc[mt][nt][1]);
            *(float2*)(C + (size_t)(row + 8) * N + col) =
                make_float2(acc[mt][nt][2], acc[mt][nt][3]);
        }
    }
}

// ---------------- tf32 mma flash attention --------------------------------
// CTA: 128 threads / 4 warps; 64 queries x 64 keys per iter; DK=64.
#define QP 68
#define VP 72
#define NTK (SEQ/64)          // 32 key tiles
#define AQ_OFF 0
#define AP_OFF (64*QP)
#define AK_OFF (2*64*QP)
#define AV_OFF (AK_OFF + 2*64*QP)
#define AM_OFF (AV_OFF + 2*64*VP)
#define ATTN_F (AM_OFF + 2*64)
#define ATTN_SMEM (ATTN_F*(int)sizeof(float))

__global__ __launch_bounds__(128) void attn_mma_kernel(
        const float* __restrict__ Q, const float* __restrict__ K,
        const float* __restrict__ V, const float* __restrict__ MF,
        float* __restrict__ O)
{
    extern __shared__ float sm[];
    float* Qs = sm + AQ_OFF;
    float* Ps = sm + AP_OFF;
    float* Kst = sm + AK_OFF;
    float* Vst = sm + AV_OFF;
    float* Mks = sm + AM_OFF;

    const int tid  = threadIdx.x;
    const int wid  = tid >> 5;
    const int lane = tid & 31;
    const int lr = lane >> 2;
    const int lc = lane & 3;
    const int wq = wid * 16;
    const int qt = blockIdx.x;
    const int h  = blockIdx.y;
    const int b  = blockIdx.z;

    const size_t qrow0 = (size_t)b * SEQ + (size_t)qt * 64;
    const float* Qg = Q + qrow0 * DMODEL + h * DKH;
    const float* Kb = K + (size_t)b * SEQ * DMODEL + h * DKH;
    const float* Vb = V + (size_t)b * SEQ * DMODEL + h * DKH;
    const float* Mb = MF + (size_t)b * SEQ;

    #pragma unroll
    for (int t = 0; t < 8; t++) {
        int idx = tid + t * 128;
        int r  = idx >> 4;
        int c4 = (idx & 15) << 2;
        float4 v = *(const float4*)(Qg + (size_t)r * DMODEL + c4);
        Qs[r * QP + c4 + 0] = __uint_as_float(f2tf32(v.x * 0.125f));
        Qs[r * QP + c4 + 1] = __uint_as_float(f2tf32(v.y * 0.125f));
        Qs[r * QP + c4 + 2] = __uint_as_float(f2tf32(v.z * 0.125f));
        Qs[r * QP + c4 + 3] = __uint_as_float(f2tf32(v.w * 0.125f));
    }

    auto load_stage = [&](int s, int kt) {
        const float* Kg = Kb + (size_t)kt * 64 * DMODEL;
        const float* Vg = Vb + (size_t)kt * 64 * DMODEL;
        uint32_t kbase = smem_u32(Kst + s * 64 * QP);
        uint32_t vbase = smem_u32(Vst + s * 64 * VP);
        #pragma unroll
        for (int t = 0; t < 8; t++) {
            int idx = tid + t * 128;
            int r = idx >> 4;
            int c = idx & 15;
            cp16(kbase + (uint32_t)(r * QP + c * 4) * 4, Kg + (size_t)r * DMODEL + c * 4);
            cp16(vbase + (uint32_t)(r * VP + c * 4) * 4, Vg + (size_t)r * DMODEL + c * 4);
        }
        if (tid < 16)   // 16 threads x 16B = 64 floats (full mask tile)
            cp16(smem_u32(Mks + s * 64) + tid * 16, Mb + kt * 64 + tid * 4);
        CP_COMMIT();
    };

    load_stage(0, 0);
    load_stage(1, 1);

    float o[8][4];
    #pragma unroll
    for (int nt = 0; nt < 8; nt++)
        #pragma unroll
        for (int i = 0; i < 4; i++) o[nt][i] = 0.0f;
    float mst0 = -1e30f, mst1 = -1e30f, lst0 = 0.0f, lst1 = 0.0f;

    for (int kt = 0; kt < NTK; kt++) {
        int s = kt & 1;
        if (kt < NTK - 1) asm volatile("cp.async.wait_group 1;" ::: "memory");
        else              asm volatile("cp.async.wait_group 0;" ::: "memory");
        __syncthreads();

        const float* Kt = Kst + s * 64 * QP;
        const float* Vt = Vst + s * 64 * VP;
        const float* mk = Mks + s * 64;

        // ---- scores: S = (Q/8) K^T ----
        float sa[8][4];
        #pragma unroll
        for (int nt = 0; nt < 8; nt++)
            #pragma unroll
            for (int i = 0; i < 4; i++) sa[nt][i] = 0.0f;

        #pragma unroll
        for (int ks = 0; ks < 8; ks++) {
            int k0 = ks * 8;
            uint32_t af[4];
            af[0] = __float_as_uint(Qs[(wq + lr) * QP + k0 + lc]);
            af[1] = __float_as_uint(Qs[(wq + lr + 8) * QP + k0 + lc]);
            af[2] = __float_as_uint(Qs[(wq + lr) * QP + k0 + lc + 4]);
            af[3] = __float_as_uint(Qs[(wq + lr + 8) * QP + k0 + lc + 4]);
            #pragma unroll
            for (int nt = 0; nt < 8; nt++) {
                uint32_t bf[2];
                bf[0] = f2tf32(Kt[(nt * 8 + lr) * QP + k0 + lc]);
                bf[1] = f2tf32(Kt[(nt * 8 + lr) * QP + k0 + lc + 4]);
                mma_tf32(sa[nt], af, bf);
            }
        }

        // ---- online softmax on accumulator layout ----
        float rm0 = -1e30f, rm1 = -1e30f;
        #pragma unroll
        for (int nt = 0; nt < 8; nt++) {
            float m0 = mk[nt * 8 + 2 * lc];
            float m1 = mk[nt * 8 + 2 * lc + 1];
            sa[nt][0] += m0; sa[nt][1] += m1;
            sa[nt][2] += m0; sa[nt][3] += m1;
            rm0 = fmaxf(rm0, fmaxf(sa[nt][0], sa[nt][1]));
            rm1 = fmaxf(rm1, fmaxf(sa[nt][2], sa[nt][3]));
        }
        rm0 = fmaxf(rm0, __shfl_xor_sync(0xffffffffu, rm0, 1));
        rm0 = fmaxf(rm0, __shfl_xor_sync(0xffffffffu, rm0, 2));
        rm1 = fmaxf(rm1, __shfl_xor_sync(0xffffffffu, rm1, 1));
        rm1 = fmaxf(rm1, __shfl_xor_sync(0xffffffffu, rm1, 2));

        float nm0 = fmaxf(mst0, rm0), nm1 = fmaxf(mst1, rm1);
        float al0 = __expf(mst0 - nm0), al1 = __expf(mst1 - nm1);
        mst0 = nm0; mst1 = nm1;

        float ps0 = 0.0f, ps1 = 0.0f;
        #pragma unroll
        for (int nt = 0; nt < 8; nt++) {
            float p0 = __expf(sa[nt][0] - nm0);
            float p1 = __expf(sa[nt][1] - nm0);
            float p2 = __expf(sa[nt][2] - nm1);
            float p3 = __expf(sa[nt][3] - nm1);
            ps0 += p0 + p1;
            ps1 += p2 + p3;
            *(float2*)(Ps + (wq + lr) * QP + nt * 8 + 2 * lc) =
                make_float2(__uint_as_float(f2tf32(p0)), __uint_as_float(f2tf32(p1)));
            *(float2*)(Ps + (wq + lr + 8) * QP + nt * 8 + 2 * lc) =
                make_float2(__uint_as_float(f2tf32(p2)), __uint_as_float(f2tf32(p3)));
            o[nt][0] *= al0; o[nt][1] *= al0;
            o[nt][2] *= al1; o[nt][3] *= al1;
        }
        ps0 += __shfl_xor_sync(0xffffffffu, ps0, 1);
        ps0 += __shfl_xor_sync(0xffffffffu, ps0, 2);
        ps1 += __shfl_xor_sync(0xffffffffu, ps1, 1);
        ps1 += __shfl_xor_sync(0xffffffffu, ps1, 2);
        lst0 = lst0 * al0 + ps0;
        lst1 = lst1 * al1 + ps1;
        __syncwarp();

        // ---- O += P V ----
        #pragma unroll
        for (int ks = 0; ks < 8; ks++) {
            int k0 = ks * 8;
            uint32_t af[4];
            af[0] = __float_as_uint(Ps[(wq + lr) * QP + k0 + lc]);
            af[1] = __float_as_uint(Ps[(wq + lr + 8) * QP + k0 + lc]);
            af[2] = __float_as_uint(Ps[(wq + lr) * QP + k0 + lc + 4]);
            af[3] = __float_as_uint(Ps[(wq + lr + 8) * QP + k0 + lc + 4]);
            #pragma unroll
            for (int nt = 0; nt < 8; nt++) {
                uint32_t bf[2];
                bf[0] = f2tf32(Vt[(k0 + lc) * VP + nt * 8 + lr]);
                bf[1] = f2tf32(Vt[(k0 + lc + 4) * VP + nt * 8 + lr]);
                mma_tf32(o[nt], af, bf);
            }
        }

        __syncthreads();
        if (kt + 2 < NTK) load_stage(s, kt + 2);
    }

    float inv0 = 1.0f / lst0;
    float inv1 = 1.0f / lst1;
    float* Og = O + qrow0 * DMODEL + h * DKH;
    #pragma unroll
    for (int nt = 0; nt < 8; nt++) {
        int col = nt * 8 + 2 * lc;
        *(float2*)(Og + (size_t)(wq + lr) * DMODEL + col) =
            make_float2(o[nt][0] * inv0, o[nt][1] * inv0);
        *(float2*)(Og + (size_t)(wq + lr + 8) * DMODEL + col) =
            make_float2(o[nt][2] * inv1, o[nt][3] * inv1);
    }
}

// ---------------- launch ---------------------------------------------------
extern "C" void kernel_launch(void* const* d_in, const int* in_sizes, int n_in,
                              void* d_out, int out_size) {
    const float* X    = (const float*)d_in[0];
    const int*   mask = (const int*)d_in[1];
    const float* Wq   = (const float*)d_in[2];
    const float* Wk   = (const float*)d_in[3];
    const float* Wv   = (const float*)d_in[4];
    const float* Wo   = (const float*)d_in[5];
    float* out = (float*)d_out;

    float *q, *k, *v, *ao, *wt, *mf;
    cudaGetSymbolAddress((void**)&q,  g_Q);
    cudaGetSymbolAddress((void**)&k,  g_K);
    cudaGetSymbolAddress((void**)&v,  g_V);
    cudaGetSymbolAddress((void**)&ao, g_AO);
    cudaGetSymbolAddress((void**)&wt, g_WT);
    cudaGetSymbolAddress((void**)&mf, g_MF);

    cudaFuncSetAttribute(attn_mma_kernel,
                         cudaFuncAttributeMaxDynamicSharedMemorySize, ATTN_SMEM);
    cudaFuncSetAttribute(tgemm_kernel,
                         cudaFuncAttributeMaxDynamicSharedMemorySize, TGEMM_SMEM);

    maskprep_kernel<<<(BATCH*SEQ + 255) / 256, 256>>>(mask, mf);

    dim3 tgrid(32, 32), tblk(32, 8);
    transpose_kernel<<<tgrid, tblk>>>(Wq, wt + 0 * DMODEL * DMODEL);
    transpose_kernel<<<tgrid, tblk>>>(Wk, wt + 1 * DMODEL * DMODEL);
    transpose_kernel<<<tgrid, tblk>>>(Wv, wt + 2 * DMODEL * DMODEL);
    transpose_kernel<<<tgrid, tblk>>>(Wo, wt + 3 * DMODEL * DMODEL);

    dim3 gg(DMODEL / 128, MTOT / 128);
    tgemm_kernel<<<gg, 256, TGEMM_SMEM>>>(X, wt + 0 * DMODEL * DMODEL, q,  MTOT, DMODEL, DMODEL);
    tgemm_kernel<<<gg, 256, TGEMM_SMEM>>>(X, wt + 1 * DMODEL * DMODEL, k,  MTOT, DMODEL, DMODEL);
    tgemm_kernel<<<gg, 256, TGEMM_SMEM>>>(X, wt + 2 * DMODEL * DMODEL, v,  MTOT, DMODEL, DMODEL);

    attn_mma_kernel<<<dim3(SEQ / 64, NHEAD, BATCH), 128, ATTN_SMEM>>>(q, k, v, mf, ao);

    tgemm_kernel<<<gg, 256, TGEMM_SMEM>>>(ao, wt + 3 * DMODEL * DMODEL, out, MTOT, DMODEL, DMODEL);
}

// round 6
// speedup vs baseline: 3.1403x; 1.0962x over previous
#include <cuda_runtime.h>
#include <cstdint>

#define DMODEL 1024
#define NHEAD 16
#define DKH 64
#define BATCH 4
#define SEQ 2048
#define MTOT (BATCH*SEQ)   // 8192
#define QKVD (3*DMODEL)    // 3072

// ---------------- scratch (static device globals; no allocation) ----------
__device__ float g_XR[MTOT*DMODEL];       // tf32-rounded input
__device__ float g_QKV[MTOT*QKVD];        // fused Q|K|V, row stride 3072
__device__ float g_AO[MTOT*DMODEL];       // attention output (tf32-rounded)
__device__ float g_WT[4*DMODEL*DMODEL];   // transposed+rounded weights [N,K]
__device__ float g_MF[BATCH*SEQ];         // additive float mask

// ---------------- helpers ---------------------------------------------------
__device__ __forceinline__ uint32_t smem_u32(const void* p) {
    uint32_t a;
    asm("{ .reg .u64 t; cvta.to.shared.u64 t, %1; cvt.u32.u64 %0, t; }"
        : "=r"(a) : "l"(p));
    return a;
}
__device__ __forceinline__ void cp16(uint32_t smem_addr, const void* gptr) {
    asm volatile("cp.async.cg.shared.global [%0], [%1], 16;"
                 :: "r"(smem_addr), "l"(gptr));
}
#define CP_COMMIT() asm volatile("cp.async.commit_group;" ::: "memory")

__device__ __forceinline__ uint32_t f2tf32(float x) {
    uint32_t r;
    asm("cvt.rna.tf32.f32 %0, %1;" : "=r"(r) : "f"(x));
    return r;
}
__device__ __forceinline__ float rnd(float x) {
    return __uint_as_float(f2tf32(x));
}
__device__ __forceinline__ void mma_tf32(float* c, const uint32_t* a,
                                         const uint32_t* b) {
    asm volatile(
        "mma.sync.aligned.m16n8k8.row.col.f32.tf32.tf32.f32 "
        "{%0,%1,%2,%3}, {%4,%5,%6,%7}, {%8,%9}, {%0,%1,%2,%3};"
        : "+f"(c[0]), "+f"(c[1]), "+f"(c[2]), "+f"(c[3])
        : "r"(a[0]), "r"(a[1]), "r"(a[2]), "r"(a[3]), "r"(b[0]), "r"(b[1]));
}

// ---------------- mask prep: int -> additive float -------------------------
__global__ void maskprep_kernel(const int* __restrict__ m, float* __restrict__ mf) {
    int i = blockIdx.x * 256 + threadIdx.x;
    if (i < BATCH * SEQ) mf[i] = (1.0f - (float)m[i]) * -1e9f;
}

// ---------------- round input X to tf32 ------------------------------------
__global__ __launch_bounds__(256) void roundx_kernel(
        const float* __restrict__ in, float* __restrict__ out)
{
    int i = blockIdx.x * 256 + threadIdx.x;      // float4 index
    float4 v = *((const float4*)in + i);
    v.x = rnd(v.x); v.y = rnd(v.y); v.z = rnd(v.z); v.w = rnd(v.w);
    *((float4*)out + i) = v;
}

// ---------------- fused transpose+round [K,N] -> [N,K] ---------------------
__global__ __launch_bounds__(256) void transpose_kernel(
        const float* __restrict__ Wq, const float* __restrict__ Wk,
        const float* __restrict__ Wv, const float* __restrict__ Wo,
        float* __restrict__ wt)
{
    __shared__ float t[32][33];
    int z = blockIdx.z;
    const float* in = (z == 0) ? Wq : (z == 1) ? Wk : (z == 2) ? Wv : Wo;
    float* out = wt + (size_t)z * DMODEL * DMODEL;
    int x = blockIdx.x * 32 + threadIdx.x;
    int y = blockIdx.y * 32 + threadIdx.y;
    #pragma unroll
    for (int j = 0; j < 32; j += 8)
        t[threadIdx.y + j][threadIdx.x] = in[(size_t)(y + j) * DMODEL + x];
    __syncthreads();
    x = blockIdx.y * 32 + threadIdx.x;
    y = blockIdx.x * 32 + threadIdx.y;
    #pragma unroll
    for (int j = 0; j < 32; j += 8)
        out[(size_t)(y + j) * DMODEL + x] = rnd(t[threadIdx.x][threadIdx.y + j]);
}

// ---------------- tf32 mma.sync GEMM: C[M,N] = A[M,K] @ Bt[N,K]^T ---------
// CTA 128x128, k-tile 32, 3-stage cp.async, inputs pre-rounded (no cvt).
#define NKT (DMODEL/32)
#define TSTR 36
#define STAGEF (2*128*TSTR)
#define TGEMM_SMEM (3*STAGEF*(int)sizeof(float))   // 110592 B

template<int ROUND>
__global__ __launch_bounds__(256) void tgemm_kernel(
        const float* __restrict__ A, const float* __restrict__ Bt,
        float* __restrict__ C, int N /* = C row stride & col space */)
{
    extern __shared__ float sm[];
    const int tid  = threadIdx.x;
    const int lane = tid & 31;
    const int wid  = tid >> 5;
    const int bm = blockIdx.y * 128;
    const int bn = blockIdx.x * 128;
    const int wm = (wid & 1) * 64;
    const int wn = (wid >> 1) * 32;
    const int K = DMODEL;

    float acc[4][4][4];
    #pragma unroll
    for (int mt = 0; mt < 4; mt++)
        #pragma unroll
        for (int nt = 0; nt < 4; nt++)
            #pragma unroll
            for (int i = 0; i < 4; i++) acc[mt][nt][i] = 0.0f;

    const float* gA = A  + (size_t)bm * K;
    const float* gB = Bt + (size_t)bn * K;

    auto load_stage = [&](int s, int kt) {
        uint32_t base = smem_u32(sm + s * STAGEF);
        uint32_t baseB = base + 128 * TSTR * 4;
        const float* pa = gA + kt * 32;
        const float* pb = gB + kt * 32;
        #pragma unroll
        for (int i = 0; i < 4; i++) {
            int idx = tid + i * 256;
            int r = idx >> 3;
            int c = idx & 7;
            uint32_t off = (uint32_t)(r * TSTR * 4 + c * 16);
            cp16(base  + off, pa + (size_t)r * K + c * 4);
            cp16(baseB + off, pb + (size_t)r * K + c * 4);
        }
        CP_COMMIT();
    };

    load_stage(0, 0);
    load_stage(1, 1);

    const int lr = lane >> 2;
    const int lc = lane & 3;

    for (int kt = 0; kt < NKT; kt++) {
        int s = kt % 3;
        if (kt < NKT - 1) asm volatile("cp.async.wait_group 1;" ::: "memory");
        else              asm volatile("cp.async.wait_group 0;" ::: "memory");
        __syncthreads();

        const float* As = sm + s * STAGEF;
        const float* Bs = As + 128 * TSTR;

        #pragma unroll
        for (int ks = 0; ks < 4; ks++) {
            int k0 = ks * 8;
            uint32_t bf[4][2];
            #pragma unroll
            for (int nt = 0; nt < 4; nt++) {
                int col = wn + nt * 8 + lr;
                bf[nt][0] = __float_as_uint(Bs[col * TSTR + k0 + lc]);
                bf[nt][1] = __float_as_uint(Bs[col * TSTR + k0 + lc + 4]);
            }
            #pragma unroll
            for (int mt = 0; mt < 4; mt++) {
                int row = wm + mt * 16 + lr;
                uint32_t af[4];
                af[0] = __float_as_uint(As[row * TSTR + k0 + lc]);
                af[1] = __float_as_uint(As[(row + 8) * TSTR + k0 + lc]);
                af[2] = __float_as_uint(As[row * TSTR + k0 + lc + 4]);
                af[3] = __float_as_uint(As[(row + 8) * TSTR + k0 + lc + 4]);
                #pragma unroll
                for (int nt = 0; nt < 4; nt++)
                    mma_tf32(acc[mt][nt], af, bf[nt]);
            }
        }
        if (kt + 2 < NKT) load_stage((kt + 2) % 3, kt + 2);
    }

    #pragma unroll
    for (int mt = 0; mt < 4; mt++) {
        int row = bm + wm + mt * 16 + lr;
        #pragma unroll
        for (int nt = 0; nt < 4; nt++) {
            int col = bn + wn + nt * 8 + 2 * lc;
            float c0 = acc[mt][nt][0], c1 = acc[mt][nt][1];
            float c2 = acc[mt][nt][2], c3 = acc[mt][nt][3];
            if (ROUND) { c0 = rnd(c0); c1 = rnd(c1); c2 = rnd(c2); c3 = rnd(c3); }
            *(float2*)(C + (size_t)row * N + col) = make_float2(c0, c1);
            *(float2*)(C + (size_t)(row + 8) * N + col) = make_float2(c2, c3);
        }
    }
}

// ---------------- tf32 mma flash attention --------------------------------
// CTA: 256 threads / 8 warps; 128 queries x 64 keys per iter; 3-stage K/V.
#define QP 68
#define VP 72
#define NTK (SEQ/64)          // 32 key tiles
#define AQ_OFF 0
#define AP_OFF (128*QP)
#define AK_OFF (2*128*QP)
#define AV_OFF (AK_OFF + 3*64*QP)
#define AM_OFF (AV_OFF + 3*64*VP)
#define ATTN_F (AM_OFF + 3*64)
#define ATTN_SMEM (ATTN_F*(int)sizeof(float))      // 177920 B

__global__ __launch_bounds__(256) void attn_mma_kernel(
        const float* __restrict__ QKV, const float* __restrict__ MF,
        float* __restrict__ O)
{
    extern __shared__ float sm[];
    float* Qs  = sm + AQ_OFF;
    float* Ps  = sm + AP_OFF;
    float* Kst = sm + AK_OFF;
    float* Vst = sm + AV_OFF;
    float* Mks = sm + AM_OFF;

    const int tid  = threadIdx.x;
    const int wid  = tid >> 5;
    const int lane = tid & 31;
    const int lr = lane >> 2;
    const int lc = lane & 3;
    const int wq = wid * 16;          // warp's query-row offset (0..112)
    const int qt = blockIdx.x;
    const int h  = blockIdx.y;
    const int b  = blockIdx.z;

    const size_t qrow0 = (size_t)b * SEQ + (size_t)qt * 128;
    const float* Qg = QKV + qrow0 * QKVD + h * DKH;
    const float* Kb = QKV + (size_t)b * SEQ * QKVD + DMODEL + h * DKH;
    const float* Vb = QKV + (size_t)b * SEQ * QKVD + 2 * DMODEL + h * DKH;
    const float* Mb = MF + (size_t)b * SEQ;

    // Q tile 128x64: pre-rounded tf32; x0.125 is exact (power of two)
    #pragma unroll
    for (int t = 0; t < 8; t++) {
        int idx = tid + t * 256;
        int r  = idx >> 4;
        int c4 = (idx & 15) << 2;
        float4 v = *(const float4*)(Qg + (size_t)r * QKVD + c4);
        Qs[r * QP + c4 + 0] = v.x * 0.125f;
        Qs[r * QP + c4 + 1] = v.y * 0.125f;
        Qs[r * QP + c4 + 2] = v.z * 0.125f;
        Qs[r * QP + c4 + 3] = v.w * 0.125f;
    }

    auto load_stage = [&](int s, int kt) {
        const float* Kg = Kb + (size_t)kt * 64 * QKVD;
        const float* Vg = Vb + (size_t)kt * 64 * QKVD;
        uint32_t kbase = smem_u32(Kst + s * 64 * QP);
        uint32_t vbase = smem_u32(Vst + s * 64 * VP);
        #pragma unroll
        for (int t = 0; t < 4; t++) {
            int idx = tid + t * 256;
            int r = idx >> 4;
            int c = idx & 15;
            cp16(kbase + (uint32_t)(r * QP + c * 4) * 4, Kg + (size_t)r * QKVD + c * 4);
            cp16(vbase + (uint32_t)(r * VP + c * 4) * 4, Vg + (size_t)r * QKVD + c * 4);
        }
        if (tid < 16)
            cp16(smem_u32(Mks + s * 64) + tid * 16, Mb + kt * 64 + tid * 4);
        CP_COMMIT();
    };

    load_stage(0, 0);
    load_stage(1, 1);

    float o[8][4];
    #pragma unroll
    for (int nt = 0; nt < 8; nt++)
        #pragma unroll
        for (int i = 0; i < 4; i++) o[nt][i] = 0.0f;
    float mst0 = -1e30f, mst1 = -1e30f, lst0 = 0.0f, lst1 = 0.0f;

    for (int kt = 0; kt < NTK; kt++) {
        int s = kt % 3;
        if (kt < NTK - 1) asm volatile("cp.async.wait_group 1;" ::: "memory");
        else              asm volatile("cp.async.wait_group 0;" ::: "memory");
        __syncthreads();

        const float* Kt = Kst + s * 64 * QP;
        const float* Vt = Vst + s * 64 * VP;
        const float* mk = Mks + s * 64;

        // ---- scores: S = (Q/8) K^T ----
        float sa[8][4];
        #pragma unroll
        for (int nt = 0; nt < 8; nt++)
            #pragma unroll
            for (int i = 0; i < 4; i++) sa[nt][i] = 0.0f;

        #pragma unroll
        for (int ks = 0; ks < 8; ks++) {
            int k0 = ks * 8;
            uint32_t af[4];
            af[0] = __float_as_uint(Qs[(wq + lr) * QP + k0 + lc]);
            af[1] = __float_as_uint(Qs[(wq + lr + 8) * QP + k0 + lc]);
            af[2] = __float_as_uint(Qs[(wq + lr) * QP + k0 + lc + 4]);
            af[3] = __float_as_uint(Qs[(wq + lr + 8) * QP + k0 + lc + 4]);
            #pragma unroll
            for (int nt = 0; nt < 8; nt++) {
                uint32_t bf[2];
                bf[0] = __float_as_uint(Kt[(nt * 8 + lr) * QP + k0 + lc]);
                bf[1] = __float_as_uint(Kt[(nt * 8 + lr) * QP + k0 + lc + 4]);
                mma_tf32(sa[nt], af, bf);
            }
        }

        // ---- online softmax on accumulator layout ----
        float rm0 = -1e30f, rm1 = -1e30f;
        #pragma unroll
        for (int nt = 0; nt < 8; nt++) {
            float m0 = mk[nt * 8 + 2 * lc];
            float m1 = mk[nt * 8 + 2 * lc + 1];
            sa[nt][0] += m0; sa[nt][1] += m1;
            sa[nt][2] += m0; sa[nt][3] += m1;
            rm0 = fmaxf(rm0, fmaxf(sa[nt][0], sa[nt][1]));
            rm1 = fmaxf(rm1, fmaxf(sa[nt][2], sa[nt][3]));
        }
        rm0 = fmaxf(rm0, __shfl_xor_sync(0xffffffffu, rm0, 1));
        rm0 = fmaxf(rm0, __shfl_xor_sync(0xffffffffu, rm0, 2));
        rm1 = fmaxf(rm1, __shfl_xor_sync(0xffffffffu, rm1, 1));
        rm1 = fmaxf(rm1, __shfl_xor_sync(0xffffffffu, rm1, 2));

        float nm0 = fmaxf(mst0, rm0), nm1 = fmaxf(mst1, rm1);
        float al0 = __expf(mst0 - nm0), al1 = __expf(mst1 - nm1);
        mst0 = nm0; mst1 = nm1;

        float ps0 = 0.0f, ps1 = 0.0f;
        #pragma unroll
        for (int nt = 0; nt < 8; nt++) {
            float p0 = __expf(sa[nt][0] - nm0);
            float p1 = __expf(sa[nt][1] - nm0);
            float p2 = __expf(sa[nt][2] - nm1);
            float p3 = __expf(sa[nt][3] - nm1);
            ps0 += p0 + p1;
            ps1 += p2 + p3;
            *(float2*)(Ps + (wq + lr) * QP + nt * 8 + 2 * lc) =
                make_float2(rnd(p0), rnd(p1));
            *(float2*)(Ps + (wq + lr + 8) * QP + nt * 8 + 2 * lc) =
                make_float2(rnd(p2), rnd(p3));
            o[nt][0] *= al0; o[nt][1] *= al0;
            o[nt][2] *= al1; o[nt][3] *= al1;
        }
        ps0 += __shfl_xor_sync(0xffffffffu, ps0, 1);
        ps0 += __shfl_xor_sync(0xffffffffu, ps0, 2);
        ps1 += __shfl_xor_sync(0xffffffffu, ps1, 1);
        ps1 += __shfl_xor_sync(0xffffffffu, ps1, 2);
        lst0 = lst0 * al0 + ps0;
        lst1 = lst1 * al1 + ps1;
        __syncwarp();

        // ---- O += P V ----
        #pragma unroll
        for (int ks = 0; ks < 8; ks++) {
            int k0 = ks * 8;
            uint32_t af[4];
            af[0] = __float_as_uint(Ps[(wq + lr) * QP + k0 + lc]);
            af[1] = __float_as_uint(Ps[(wq + lr + 8) * QP + k0 + lc]);
            af[2] = __float_as_uint(Ps[(wq + lr) * QP + k0 + lc + 4]);
            af[3] = __float_as_uint(Ps[(wq + lr + 8) * QP + k0 + lc + 4]);
            #pragma unroll
            for (int nt = 0; nt < 8; nt++) {
                uint32_t bf[2];
                bf[0] = __float_as_uint(Vt[(k0 + lc) * VP + nt * 8 + lr]);
                bf[1] = __float_as_uint(Vt[(k0 + lc + 4) * VP + nt * 8 + lr]);
                mma_tf32(o[nt], af, bf);
            }
        }

        if (kt + 2 < NTK) load_stage((kt + 2) % 3, kt + 2);
    }

    float inv0 = 1.0f / lst0;
    float inv1 = 1.0f / lst1;
    float* Og = O + qrow0 * DMODEL + h * DKH;
    #pragma unroll
    for (int nt = 0; nt < 8; nt++) {
        int col = nt * 8 + 2 * lc;
        *(float2*)(Og + (size_t)(wq + lr) * DMODEL + col) =
            make_float2(rnd(o[nt][0] * inv0), rnd(o[nt][1] * inv0));
        *(float2*)(Og + (size_t)(wq + lr + 8) * DMODEL + col) =
            make_float2(rnd(o[nt][2] * inv1), rnd(o[nt][3] * inv1));
    }
}

// ---------------- launch ---------------------------------------------------
extern "C" void kernel_launch(void* const* d_in, const int* in_sizes, int n_in,
                              void* d_out, int out_size) {
    const float* X    = (const float*)d_in[0];
    const int*   mask = (const int*)d_in[1];
    const float* Wq   = (const float*)d_in[2];
    const float* Wk   = (const float*)d_in[3];
    const float* Wv   = (const float*)d_in[4];
    const float* Wo   = (const float*)d_in[5];
    float* out = (float*)d_out;

    float *xr, *qkv, *ao, *wt, *mf;
    cudaGetSymbolAddress((void**)&xr,  g_XR);
    cudaGetSymbolAddress((void**)&qkv, g_QKV);
    cudaGetSymbolAddress((void**)&ao,  g_AO);
    cudaGetSymbolAddress((void**)&wt,  g_WT);
    cudaGetSymbolAddress((void**)&mf,  g_MF);

    cudaFuncSetAttribute(attn_mma_kernel,
                         cudaFuncAttributeMaxDynamicSharedMemorySize, ATTN_SMEM);
    cudaFuncSetAttribute(tgemm_kernel<0>,
                         cudaFuncAttributeMaxDynamicSharedMemorySize, TGEMM_SMEM);
    cudaFuncSetAttribute(tgemm_kernel<1>,
                         cudaFuncAttributeMaxDynamicSharedMemorySize, TGEMM_SMEM);

    maskprep_kernel<<<(BATCH*SEQ + 255) / 256, 256>>>(mask, mf);
    roundx_kernel<<<MTOT * DMODEL / 4 / 256, 256>>>(X, xr);
    transpose_kernel<<<dim3(32, 32, 4), dim3(32, 8)>>>(Wq, Wk, Wv, Wo, wt);

    // fused Q|K|V projection: [8192,1024] @ [1024,3072] -> [8192,3072]
    tgemm_kernel<1><<<dim3(QKVD / 128, MTOT / 128), 256, TGEMM_SMEM>>>(
        xr, wt, qkv, QKVD);

    attn_mma_kernel<<<dim3(SEQ / 128, NHEAD, BATCH), 256, ATTN_SMEM>>>(qkv, mf, ao);

    tgemm_kernel<0><<<dim3(DMODEL / 128, MTOT / 128), 256, TGEMM_SMEM>>>(
        ao, wt + 3 * DMODEL * DMODEL, out, DMODEL);
}

// round 7
// speedup vs baseline: 6.6574x; 2.1200x over previous
#include <cuda_runtime.h>
#include <cuda_fp16.h>
#include <cstdint>

#define DMODEL 1024
#define NHEAD 16
#define DKH 64
#define BATCH 4
#define SEQ 2048
#define MTOT (BATCH*SEQ)   // 8192
#define QKVD (3*DMODEL)    // 3072
#define STR 72             // smem row stride in halves (144B = 9*16B)

// ---------------- scratch (static device globals; no allocation) ----------
__device__ __align__(16) __half g_XH[MTOT*DMODEL];
__device__ __align__(16) __half g_QKVH[MTOT*QKVD];
__device__ __align__(16) __half g_AOH[MTOT*DMODEL];
__device__ __align__(16) __half g_WTH[4*DMODEL*DMODEL];  // transposed [N,K] fp16
__device__ float g_MF[BATCH*SEQ];                        // additive float mask

// ---------------- helpers ---------------------------------------------------
__device__ __forceinline__ uint32_t smem_u32(const void* p) {
    uint32_t a;
    asm("{ .reg .u64 t; cvta.to.shared.u64 t, %1; cvt.u32.u64 %0, t; }"
        : "=r"(a) : "l"(p));
    return a;
}
__device__ __forceinline__ void cp16(uint32_t smem_addr, const void* gptr) {
    asm volatile("cp.async.cg.shared.global [%0], [%1], 16;"
                 :: "r"(smem_addr), "l"(gptr));
}
#define CP_COMMIT() asm volatile("cp.async.commit_group;" ::: "memory")

__device__ __forceinline__ void ldmx4(uint32_t* r, uint32_t addr) {
    asm volatile("ldmatrix.sync.aligned.m8n8.x4.shared.b16 {%0,%1,%2,%3}, [%4];"
        : "=r"(r[0]), "=r"(r[1]), "=r"(r[2]), "=r"(r[3]) : "r"(addr));
}
__device__ __forceinline__ void ldmx4t(uint32_t* r, uint32_t addr) {
    asm volatile("ldmatrix.sync.aligned.m8n8.x4.trans.shared.b16 {%0,%1,%2,%3}, [%4];"
        : "=r"(r[0]), "=r"(r[1]), "=r"(r[2]), "=r"(r[3]) : "r"(addr));
}
__device__ __forceinline__ void mma_f16(float* c, const uint32_t* a,
                                        const uint32_t* b) {
    asm volatile(
        "mma.sync.aligned.m16n8k16.row.col.f32.f16.f16.f32 "
        "{%0,%1,%2,%3}, {%4,%5,%6,%7}, {%8,%9}, {%0,%1,%2,%3};"
        : "+f"(c[0]), "+f"(c[1]), "+f"(c[2]), "+f"(c[3])
        : "r"(a[0]), "r"(a[1]), "r"(a[2]), "r"(a[3]), "r"(b[0]), "r"(b[1]));
}

// ---------------- mask prep -------------------------------------------------
__global__ void maskprep_kernel(const int* __restrict__ m, float* __restrict__ mf) {
    int i = blockIdx.x * 256 + threadIdx.x;
    if (i < BATCH * SEQ) mf[i] = (1.0f - (float)m[i]) * -1e9f;
}

// ---------------- X fp32 -> fp16 -------------------------------------------
__global__ __launch_bounds__(256) void xtohalf_kernel(
        const float* __restrict__ in, __half* __restrict__ out)
{
    int i = blockIdx.x * 256 + threadIdx.x;   // float4 index
    float4 v = ((const float4*)in)[i];
    __half2 h0 = __floats2half2_rn(v.x, v.y);
    __half2 h1 = __floats2half2_rn(v.z, v.w);
    ((__half2*)out)[2*i]   = h0;
    ((__half2*)out)[2*i+1] = h1;
}

// ---------------- fused transpose [K,N]->[N,K] + fp16 ----------------------
__global__ __launch_bounds__(256) void transpose_kernel(
        const float* __restrict__ Wq, const float* __restrict__ Wk,
        const float* __restrict__ Wv, const float* __restrict__ Wo,
        __half* __restrict__ wt)
{
    __shared__ float t[32][33];
    int z = blockIdx.z;
    const float* in = (z == 0) ? Wq : (z == 1) ? Wk : (z == 2) ? Wv : Wo;
    __half* out = wt + (size_t)z * DMODEL * DMODEL;
    int x = blockIdx.x * 32 + threadIdx.x;
    int y = blockIdx.y * 32 + threadIdx.y;
    #pragma unroll
    for (int j = 0; j < 32; j += 8)
        t[threadIdx.y + j][threadIdx.x] = in[(size_t)(y + j) * DMODEL + x];
    __syncthreads();
    x = blockIdx.y * 32 + threadIdx.x;
    y = blockIdx.x * 32 + threadIdx.y;
    #pragma unroll
    for (int j = 0; j < 32; j += 8)
        out[(size_t)(y + j) * DMODEL + x] =
            __float2half_rn(t[threadIdx.x][threadIdx.y + j]);
}

// ---------------- fp16 mma GEMM: C[M,N] = A[M,K] @ Bt[N,K]^T ----------------
// CTA 128x128, k-tile 64 halves, 3-stage cp.async, ldmatrix fragments.
#define NKT2 (DMODEL/64)                     // 16 k-tiles
#define STAGE_BYTES (2*128*STR*2)            // A+B tiles: 36864 B
#define TGEMM_SMEM (3*STAGE_BYTES)           // 110592 B

template<int HOUT>
__global__ __launch_bounds__(256, 2) void tgemm_h_kernel(
        const __half* __restrict__ A, const __half* __restrict__ Bt,
        void* __restrict__ Cv, int N)
{
    extern __shared__ char smb[];
    const int tid  = threadIdx.x;
    const int lane = tid & 31;
    const int wid  = tid >> 5;
    const int bm = blockIdx.y * 128;
    const int bn = blockIdx.x * 128;
    const int wm = (wid & 1) * 64;
    const int wn = (wid >> 1) * 32;
    const int K = DMODEL;

    float acc[4][4][4];
    #pragma unroll
    for (int mt = 0; mt < 4; mt++)
        #pragma unroll
        for (int nt = 0; nt < 4; nt++)
            #pragma unroll
            for (int i = 0; i < 4; i++) acc[mt][nt][i] = 0.0f;

    const __half* gA = A  + (size_t)bm * K;
    const __half* gB = Bt + (size_t)bn * K;

    auto load_stage = [&](int s, int kt) {
        uint32_t base  = smem_u32(smb) + s * STAGE_BYTES;
        uint32_t baseB = base + 128 * STR * 2;
        const __half* pa = gA + kt * 64;
        const __half* pb = gB + kt * 64;
        #pragma unroll
        for (int i = 0; i < 4; i++) {
            int idx = tid + i * 256;           // 0..1023
            int r = idx >> 3;                  // 0..127
            int c = idx & 7;                   // 16B chunk (8 halves)
            uint32_t off = (uint32_t)(r * STR * 2 + c * 16);
            cp16(base  + off, pa + (size_t)r * K + c * 8);
            cp16(baseB + off, pb + (size_t)r * K + c * 8);
        }
        CP_COMMIT();
    };

    load_stage(0, 0);
    load_stage(1, 1);

    const int lr = lane >> 2;
    const int lc = lane & 3;
    // ldmatrix lane->address mapping
    const int a_row = (lane & 7) + ((lane >> 3) & 1) * 8;   // A x4: row offset
    const int a_k   = (lane >> 4) * 8;                      // A x4: k offset
    const int b_row = (lane & 7) + (lane >> 4) * 8;         // B x4: n-row offset
    const int b_k   = ((lane >> 3) & 1) * 8;                // B x4: k offset

    for (int kt = 0; kt < NKT2; kt++) {
        int s = kt % 3;
        if (kt < NKT2 - 1) asm volatile("cp.async.wait_group 1;" ::: "memory");
        else               asm volatile("cp.async.wait_group 0;" ::: "memory");
        __syncthreads();

        const __half* As = (const __half*)(smb + s * STAGE_BYTES);
        const __half* Bs = As + 128 * STR;

        #pragma unroll
        for (int ks = 0; ks < 4; ks++) {
            int k0 = ks * 16;
            uint32_t a[4][4], b[2][4];
            #pragma unroll
            for (int mt = 0; mt < 4; mt++)
                ldmx4(a[mt], smem_u32(As + (wm + mt * 16 + a_row) * STR + k0 + a_k));
            #pragma unroll
            for (int ntp = 0; ntp < 2; ntp++)
                ldmx4(b[ntp], smem_u32(Bs + (wn + ntp * 16 + b_row) * STR + k0 + b_k));
            #pragma unroll
            for (int mt = 0; mt < 4; mt++) {
                mma_f16(acc[mt][0], a[mt], &b[0][0]);
                mma_f16(acc[mt][1], a[mt], &b[0][2]);
                mma_f16(acc[mt][2], a[mt], &b[1][0]);
                mma_f16(acc[mt][3], a[mt], &b[1][2]);
            }
        }
        if (kt + 2 < NKT2) load_stage((kt + 2) % 3, kt + 2);
    }

    #pragma unroll
    for (int mt = 0; mt < 4; mt++) {
        int row = bm + wm + mt * 16 + lr;
        #pragma unroll
        for (int nt = 0; nt < 4; nt++) {
            int col = bn + wn + nt * 8 + 2 * lc;
            if (HOUT) {
                __half* C = (__half*)Cv;
                *(__half2*)(C + (size_t)row * N + col) =
                    __floats2half2_rn(acc[mt][nt][0], acc[mt][nt][1]);
                *(__half2*)(C + (size_t)(row + 8) * N + col) =
                    __floats2half2_rn(acc[mt][nt][2], acc[mt][nt][3]);
            } else {
                float* C = (float*)Cv;
                *(float2*)(C + (size_t)row * N + col) =
                    make_float2(acc[mt][nt][0], acc[mt][nt][1]);
                *(float2*)(C + (size_t)(row + 8) * N + col) =
                    make_float2(acc[mt][nt][2], acc[mt][nt][3]);
            }
        }
    }
}

// ---------------- fp16 mma flash attention ---------------------------------
// CTA: 256 threads / 8 warps; 128 queries x 64 keys per iter; 3-stage K/V.
#define NTK (SEQ/64)
#define AQ_BYTES (128*STR*2)
#define AK_BYTES (64*STR*2)
#define ATTN_SMEM (2*AQ_BYTES + 3*2*AK_BYTES + 3*64*(int)sizeof(float))

__global__ __launch_bounds__(256, 2) void attn_mma_kernel(
        const __half* __restrict__ QKV, const float* __restrict__ MF,
        __half* __restrict__ O)
{
    extern __shared__ char smb[];
    __half* Qs  = (__half*)smb;
    __half* Ps  = Qs + 128 * STR;
    __half* Kss = Ps + 128 * STR;          // 3 stages
    __half* Vss = Kss + 3 * 64 * STR;      // 3 stages
    float*  Mks = (float*)(Vss + 3 * 64 * STR);

    const int tid  = threadIdx.x;
    const int wid  = tid >> 5;
    const int lane = tid & 31;
    const int lr = lane >> 2;
    const int lc = lane & 3;
    const int wq = wid * 16;
    const int qt = blockIdx.x;
    const int h  = blockIdx.y;
    const int b  = blockIdx.z;

    const int a_row = (lane & 7) + ((lane >> 3) & 1) * 8;
    const int a_k   = (lane >> 4) * 8;
    const int b_row = (lane & 7) + (lane >> 4) * 8;
    const int b_k   = ((lane >> 3) & 1) * 8;

    const size_t qrow0 = (size_t)b * SEQ + (size_t)qt * 128;
    const __half* Qg = QKV + qrow0 * QKVD + h * DKH;
    const __half* Kb = QKV + (size_t)b * SEQ * QKVD + DMODEL + h * DKH;
    const __half* Vb = QKV + (size_t)b * SEQ * QKVD + 2 * DMODEL + h * DKH;
    const float* Mb = MF + (size_t)b * SEQ;

    // Q tile 128x64 fp16, scale by 0.125 (exact power of two in fp16)
    const __half2 sc = __float2half2_rn(0.125f);
    #pragma unroll
    for (int t = 0; t < 4; t++) {
        int idx = tid + t * 256;           // 0..1023
        int r = idx >> 3;
        int c = idx & 7;
        union { uint4 u; __half2 h[4]; } v;
        v.u = *(const uint4*)(Qg + (size_t)r * QKVD + c * 8);
        #pragma unroll
        for (int j = 0; j < 4; j++) v.h[j] = __hmul2(v.h[j], sc);
        *(uint4*)(Qs + r * STR + c * 8) = v.u;
    }

    auto load_stage = [&](int s, int kt) {
        const __half* Kg = Kb + (size_t)kt * 64 * QKVD;
        const __half* Vg = Vb + (size_t)kt * 64 * QKVD;
        uint32_t kbase = smem_u32(Kss + s * 64 * STR);
        uint32_t vbase = smem_u32(Vss + s * 64 * STR);
        #pragma unroll
        for (int t = 0; t < 2; t++) {
            int idx = tid + t * 256;       // 0..511
            int r = idx >> 3;
            int c = idx & 7;
            uint32_t off = (uint32_t)(r * STR * 2 + c * 16);
            cp16(kbase + off, Kg + (size_t)r * QKVD + c * 8);
            cp16(vbase + off, Vg + (size_t)r * QKVD + c * 8);
        }
        if (tid < 16)
            cp16(smem_u32(Mks + s * 64) + tid * 16, Mb + kt * 64 + tid * 4);
        CP_COMMIT();
    };

    load_stage(0, 0);
    load_stage(1, 1);

    float o[8][4];
    #pragma unroll
    for (int nt = 0; nt < 8; nt++)
        #pragma unroll
        for (int i = 0; i < 4; i++) o[nt][i] = 0.0f;
    float mst0 = -1e30f, mst1 = -1e30f, lst0 = 0.0f, lst1 = 0.0f;

    for (int kt = 0; kt < NTK; kt++) {
        int s = kt % 3;
        if (kt < NTK - 1) asm volatile("cp.async.wait_group 1;" ::: "memory");
        else              asm volatile("cp.async.wait_group 0;" ::: "memory");
        __syncthreads();

        const __half* Kt = Kss + s * 64 * STR;
        const __half* Vt = Vss + s * 64 * STR;
        const float* mk = Mks + s * 64;

        // ---- scores: S = (Q/8) K^T ----
        float sa[8][4];
        #pragma unroll
        for (int nt = 0; nt < 8; nt++)
            #pragma unroll
            for (int i = 0; i < 4; i++) sa[nt][i] = 0.0f;

        #pragma unroll
        for (int ks = 0; ks < 4; ks++) {
            int k0 = ks * 16;
            uint32_t a[4];
            ldmx4(a, smem_u32(Qs + (wq + a_row) * STR + k0 + a_k));
            #pragma unroll
            for (int ntp = 0; ntp < 4; ntp++) {
                uint32_t bb[4];
                ldmx4(bb, smem_u32(Kt + (ntp * 16 + b_row) * STR + k0 + b_k));
                mma_f16(sa[2 * ntp],     a, &bb[0]);
                mma_f16(sa[2 * ntp + 1], a, &bb[2]);
            }
        }

        // ---- online softmax on accumulator layout ----
        float rm0 = -1e30f, rm1 = -1e30f;
        #pragma unroll
        for (int nt = 0; nt < 8; nt++) {
            float m0 = mk[nt * 8 + 2 * lc];
            float m1 = mk[nt * 8 + 2 * lc + 1];
            sa[nt][0] += m0; sa[nt][1] += m1;
            sa[nt][2] += m0; sa[nt][3] += m1;
            rm0 = fmaxf(rm0, fmaxf(sa[nt][0], sa[nt][1]));
            rm1 = fmaxf(rm1, fmaxf(sa[nt][2], sa[nt][3]));
        }
        rm0 = fmaxf(rm0, __shfl_xor_sync(0xffffffffu, rm0, 1));
        rm0 = fmaxf(rm0, __shfl_xor_sync(0xffffffffu, rm0, 2));
        rm1 = fmaxf(rm1, __shfl_xor_sync(0xffffffffu, rm1, 1));
        rm1 = fmaxf(rm1, __shfl_xor_sync(0xffffffffu, rm1, 2));

        float nm0 = fmaxf(mst0, rm0), nm1 = fmaxf(mst1, rm1);
        float al0 = __expf(mst0 - nm0), al1 = __expf(mst1 - nm1);
        mst0 = nm0; mst1 = nm1;

        float ps0 = 0.0f, ps1 = 0.0f;
        #pragma unroll
        for (int nt = 0; nt < 8; nt++) {
            float p0 = __expf(sa[nt][0] - nm0);
            float p1 = __expf(sa[nt][1] - nm0);
            float p2 = __expf(sa[nt][2] - nm1);
            float p3 = __expf(sa[nt][3] - nm1);
            ps0 += p0 + p1;
            ps1 += p2 + p3;
            *(__half2*)(Ps + (wq + lr) * STR + nt * 8 + 2 * lc) =
                __floats2half2_rn(p0, p1);
            *(__half2*)(Ps + (wq + lr + 8) * STR + nt * 8 + 2 * lc) =
                __floats2half2_rn(p2, p3);
            o[nt][0] *= al0; o[nt][1] *= al0;
            o[nt][2] *= al1; o[nt][3] *= al1;
        }
        ps0 += __shfl_xor_sync(0xffffffffu, ps0, 1);
        ps0 += __shfl_xor_sync(0xffffffffu, ps0, 2);
        ps1 += __shfl_xor_sync(0xffffffffu, ps1, 1);
        ps1 += __shfl_xor_sync(0xffffffffu, ps1, 2);
        lst0 = lst0 * al0 + ps0;
        lst1 = lst1 * al1 + ps1;
        __syncwarp();

        // ---- O += P V  (V via ldmatrix.trans) ----
        #pragma unroll
        for (int ks = 0; ks < 4; ks++) {
            int k0 = ks * 16;
            uint32_t a[4];
            ldmx4(a, smem_u32(Ps + (wq + a_row) * STR + k0 + a_k));
            #pragma unroll
            for (int ntp = 0; ntp < 4; ntp++) {
                uint32_t bb[4];
                ldmx4t(bb, smem_u32(Vt + (k0 + a_row) * STR + ntp * 16 + a_k));
                mma_f16(o[2 * ntp],     a, &bb[0]);
                mma_f16(o[2 * ntp + 1], a, &bb[2]);
            }
        }

        if (kt + 2 < NTK) load_stage((kt + 2) % 3, kt + 2);
    }

    float inv0 = 1.0f / lst0;
    float inv1 = 1.0f / lst1;
    __half* Og = O + qrow0 * DMODEL + h * DKH;
    #pragma unroll
    for (int nt = 0; nt < 8; nt++) {
        int col = nt * 8 + 2 * lc;
        *(__half2*)(Og + (size_t)(wq + lr) * DMODEL + col) =
            __floats2half2_rn(o[nt][0] * inv0, o[nt][1] * inv0);
        *(__half2*)(Og + (size_t)(wq + lr + 8) * DMODEL + col) =
            __floats2half2_rn(o[nt][2] * inv1, o[nt][3] * inv1);
    }
}

// ---------------- launch ---------------------------------------------------
extern "C" void kernel_launch(void* const* d_in, const int* in_sizes, int n_in,
                              void* d_out, int out_size) {
    const float* X    = (const float*)d_in[0];
    const int*   mask = (const int*)d_in[1];
    const float* Wq   = (const float*)d_in[2];
    const float* Wk   = (const float*)d_in[3];
    const float* Wv   = (const float*)d_in[4];
    const float* Wo   = (const float*)d_in[5];
    float* out = (float*)d_out;

    __half *xh, *qkvh, *aoh, *wth;
    float *mf;
    cudaGetSymbolAddress((void**)&xh,   g_XH);
    cudaGetSymbolAddress((void**)&qkvh, g_QKVH);
    cudaGetSymbolAddress((void**)&aoh,  g_AOH);
    cudaGetSymbolAddress((void**)&wth,  g_WTH);
    cudaGetSymbolAddress((void**)&mf,   g_MF);

    cudaFuncSetAttribute(attn_mma_kernel,
                         cudaFuncAttributeMaxDynamicSharedMemorySize, ATTN_SMEM);
    cudaFuncSetAttribute(tgemm_h_kernel<0>,
                         cudaFuncAttributeMaxDynamicSharedMemorySize, TGEMM_SMEM);
    cudaFuncSetAttribute(tgemm_h_kernel<1>,
                         cudaFuncAttributeMaxDynamicSharedMemorySize, TGEMM_SMEM);

    maskprep_kernel<<<(BATCH*SEQ + 255) / 256, 256>>>(mask, mf);
    xtohalf_kernel<<<MTOT * DMODEL / 4 / 256, 256>>>(X, xh);
    transpose_kernel<<<dim3(32, 32, 4), dim3(32, 8)>>>(Wq, Wk, Wv, Wo, wth);

    // fused Q|K|V projection: [8192,1024] @ [1024,3072] -> fp16 [8192,3072]
    tgemm_h_kernel<1><<<dim3(QKVD / 128, MTOT / 128), 256, TGEMM_SMEM>>>(
        xh, wth, qkvh, QKVD);

    attn_mma_kernel<<<dim3(SEQ / 128, NHEAD, BATCH), 256, ATTN_SMEM>>>(qkvh, mf, aoh);

    // output projection: fp16 inputs -> fp32 out
    tgemm_h_kernel<0><<<dim3(DMODEL / 128, MTOT / 128), 256, TGEMM_SMEM>>>(
        aoh, wth + 3 * DMODEL * DMODEL, out, DMODEL);
}

// round 8
// speedup vs baseline: 7.2567x; 1.0900x over previous
#include <cuda_runtime.h>
#include <cuda_fp16.h>
#include <cstdint>

#define DMODEL 1024
#define NHEAD 16
#define DKH 64
#define BATCH 4
#define SEQ 2048
#define MTOT (BATCH*SEQ)   // 8192
#define QKVD (3*DMODEL)    // 3072
#define STR 72             // smem row stride in halves (144B = 9*16B)
#define LOG2E 1.4426950408889634f

// ---------------- scratch (static device globals; no allocation) ----------
__device__ __align__(16) __half g_XH[MTOT*DMODEL];
__device__ __align__(16) __half g_QKVH[MTOT*QKVD];
__device__ __align__(16) __half g_AOH[MTOT*DMODEL];
__device__ __align__(16) __half g_WTH[4*DMODEL*DMODEL];  // transposed [N,K] fp16
__device__ float g_MF[BATCH*SEQ];                        // additive mask (log2 domain)

// ---------------- helpers ---------------------------------------------------
__device__ __forceinline__ uint32_t smem_u32(const void* p) {
    uint32_t a;
    asm("{ .reg .u64 t; cvta.to.shared.u64 t, %1; cvt.u32.u64 %0, t; }"
        : "=r"(a) : "l"(p));
    return a;
}
__device__ __forceinline__ void cp16(uint32_t smem_addr, const void* gptr) {
    asm volatile("cp.async.cg.shared.global [%0], [%1], 16;"
                 :: "r"(smem_addr), "l"(gptr));
}
#define CP_COMMIT() asm volatile("cp.async.commit_group;" ::: "memory")

__device__ __forceinline__ void ldmx4(uint32_t* r, uint32_t addr) {
    asm volatile("ldmatrix.sync.aligned.m8n8.x4.shared.b16 {%0,%1,%2,%3}, [%4];"
        : "=r"(r[0]), "=r"(r[1]), "=r"(r[2]), "=r"(r[3]) : "r"(addr));
}
__device__ __forceinline__ void ldmx4t(uint32_t* r, uint32_t addr) {
    asm volatile("ldmatrix.sync.aligned.m8n8.x4.trans.shared.b16 {%0,%1,%2,%3}, [%4];"
        : "=r"(r[0]), "=r"(r[1]), "=r"(r[2]), "=r"(r[3]) : "r"(addr));
}
__device__ __forceinline__ void mma_f16(float* c, const uint32_t* a,
                                        const uint32_t* b) {
    asm volatile(
        "mma.sync.aligned.m16n8k16.row.col.f32.f16.f16.f32 "
        "{%0,%1,%2,%3}, {%4,%5,%6,%7}, {%8,%9}, {%0,%1,%2,%3};"
        : "+f"(c[0]), "+f"(c[1]), "+f"(c[2]), "+f"(c[3])
        : "r"(a[0]), "r"(a[1]), "r"(a[2]), "r"(a[3]), "r"(b[0]), "r"(b[1]));
}
__device__ __forceinline__ uint32_t packh2(float a, float b) {
    __half2 h = __floats2half2_rn(a, b);
    return *(uint32_t*)&h;
}

// ---------------- mask prep (log2 domain) -----------------------------------
__global__ void maskprep_kernel(const int* __restrict__ m, float* __restrict__ mf) {
    int i = blockIdx.x * 256 + threadIdx.x;
    if (i < BATCH * SEQ) mf[i] = (1.0f - (float)m[i]) * (-1e9f * LOG2E);
}

// ---------------- X fp32 -> fp16 -------------------------------------------
__global__ __launch_bounds__(256) void xtohalf_kernel(
        const float* __restrict__ in, __half* __restrict__ out)
{
    int i = blockIdx.x * 256 + threadIdx.x;
    float4 v = ((const float4*)in)[i];
    ((__half2*)out)[2*i]   = __floats2half2_rn(v.x, v.y);
    ((__half2*)out)[2*i+1] = __floats2half2_rn(v.z, v.w);
}

// ---------------- fused transpose [K,N]->[N,K] + fp16 ----------------------
__global__ __launch_bounds__(256) void transpose_kernel(
        const float* __restrict__ Wq, const float* __restrict__ Wk,
        const float* __restrict__ Wv, const float* __restrict__ Wo,
        __half* __restrict__ wt)
{
    __shared__ float t[32][33];
    int z = blockIdx.z;
    const float* in = (z == 0) ? Wq : (z == 1) ? Wk : (z == 2) ? Wv : Wo;
    __half* out = wt + (size_t)z * DMODEL * DMODEL;
    int x = blockIdx.x * 32 + threadIdx.x;
    int y = blockIdx.y * 32 + threadIdx.y;
    #pragma unroll
    for (int j = 0; j < 32; j += 8)
        t[threadIdx.y + j][threadIdx.x] = in[(size_t)(y + j) * DMODEL + x];
    __syncthreads();
    x = blockIdx.y * 32 + threadIdx.x;
    y = blockIdx.x * 32 + threadIdx.y;
    #pragma unroll
    for (int j = 0; j < 32; j += 8)
        out[(size_t)(y + j) * DMODEL + x] =
            __float2half_rn(t[threadIdx.x][threadIdx.y + j]);
}

// ---------------- fp16 mma GEMM: C[M,N] = A[M,K] @ Bt[N,K]^T ----------------
#define NKT2 (DMODEL/64)
#define STAGE_BYTES (2*128*STR*2)
#define TGEMM_SMEM (3*STAGE_BYTES)

template<int HOUT>
__global__ __launch_bounds__(256, 2) void tgemm_h_kernel(
        const __half* __restrict__ A, const __half* __restrict__ Bt,
        void* __restrict__ Cv, int N, int qcols, float qscale)
{
    extern __shared__ char smb[];
    const int tid  = threadIdx.x;
    const int lane = tid & 31;
    const int wid  = tid >> 5;
    const int bm = blockIdx.y * 128;
    const int bn = blockIdx.x * 128;
    const int wm = (wid & 1) * 64;
    const int wn = (wid >> 1) * 32;
    const int K = DMODEL;

    float acc[4][4][4];
    #pragma unroll
    for (int mt = 0; mt < 4; mt++)
        #pragma unroll
        for (int nt = 0; nt < 4; nt++)
            #pragma unroll
            for (int i = 0; i < 4; i++) acc[mt][nt][i] = 0.0f;

    const __half* gA = A  + (size_t)bm * K;
    const __half* gB = Bt + (size_t)bn * K;

    auto load_stage = [&](int s, int kt) {
        uint32_t base  = smem_u32(smb) + s * STAGE_BYTES;
        uint32_t baseB = base + 128 * STR * 2;
        const __half* pa = gA + kt * 64;
        const __half* pb = gB + kt * 64;
        #pragma unroll
        for (int i = 0; i < 4; i++) {
            int idx = tid + i * 256;
            int r = idx >> 3;
            int c = idx & 7;
            uint32_t off = (uint32_t)(r * STR * 2 + c * 16);
            cp16(base  + off, pa + (size_t)r * K + c * 8);
            cp16(baseB + off, pb + (size_t)r * K + c * 8);
        }
        CP_COMMIT();
    };

    load_stage(0, 0);
    load_stage(1, 1);

    const int lr = lane >> 2;
    const int lc = lane & 3;
    const int a_row = (lane & 7) + ((lane >> 3) & 1) * 8;
    const int a_k   = (lane >> 4) * 8;
    const int b_row = (lane & 7) + (lane >> 4) * 8;
    const int b_k   = ((lane >> 3) & 1) * 8;

    for (int kt = 0; kt < NKT2; kt++) {
        int s = kt % 3;
        if (kt < NKT2 - 1) asm volatile("cp.async.wait_group 1;" ::: "memory");
        else               asm volatile("cp.async.wait_group 0;" ::: "memory");
        __syncthreads();

        const __half* As = (const __half*)(smb + s * STAGE_BYTES);
        const __half* Bs = As + 128 * STR;

        #pragma unroll
        for (int ks = 0; ks < 4; ks++) {
            int k0 = ks * 16;
            uint32_t a[4][4], b[2][4];
            #pragma unroll
            for (int mt = 0; mt < 4; mt++)
                ldmx4(a[mt], smem_u32(As + (wm + mt * 16 + a_row) * STR + k0 + a_k));
            #pragma unroll
            for (int ntp = 0; ntp < 2; ntp++)
                ldmx4(b[ntp], smem_u32(Bs + (wn + ntp * 16 + b_row) * STR + k0 + b_k));
            #pragma unroll
            for (int mt = 0; mt < 4; mt++) {
                mma_f16(acc[mt][0], a[mt], &b[0][0]);
                mma_f16(acc[mt][1], a[mt], &b[0][2]);
                mma_f16(acc[mt][2], a[mt], &b[1][0]);
                mma_f16(acc[mt][3], a[mt], &b[1][2]);
            }
        }
        if (kt + 2 < NKT2) load_stage((kt + 2) % 3, kt + 2);
    }

    const float sc = (bn < qcols) ? qscale : 1.0f;
    #pragma unroll
    for (int mt = 0; mt < 4; mt++) {
        int row = bm + wm + mt * 16 + lr;
        #pragma unroll
        for (int nt = 0; nt < 4; nt++) {
            int col = bn + wn + nt * 8 + 2 * lc;
            float c0 = acc[mt][nt][0] * sc, c1 = acc[mt][nt][1] * sc;
            float c2 = acc[mt][nt][2] * sc, c3 = acc[mt][nt][3] * sc;
            if (HOUT) {
                __half* C = (__half*)Cv;
                *(__half2*)(C + (size_t)row * N + col) = __floats2half2_rn(c0, c1);
                *(__half2*)(C + (size_t)(row + 8) * N + col) = __floats2half2_rn(c2, c3);
            } else {
                float* C = (float*)Cv;
                *(float2*)(C + (size_t)row * N + col) = make_float2(c0, c1);
                *(float2*)(C + (size_t)(row + 8) * N + col) = make_float2(c2, c3);
            }
        }
    }
}

// ---------------- fp16 mma flash attention ---------------------------------
// CTA: 256 threads / 8 warps; 128 q x 64 k per iter; 4-stage K/V, P in regs.
#define NTK (SEQ/64)
#define NSTG 4
#define AQ_HALVES (128*STR)
#define AK_HALVES (64*STR)
#define ATTN_SMEM ((AQ_HALVES + NSTG*2*AK_HALVES)*2 + NSTG*64*(int)sizeof(float))

__global__ __launch_bounds__(256, 2) void attn_mma_kernel(
        const __half* __restrict__ QKV, const float* __restrict__ MF,
        __half* __restrict__ O)
{
    extern __shared__ char smb[];
    __half* Qs  = (__half*)smb;
    __half* Kss = Qs + AQ_HALVES;
    __half* Vss = Kss + NSTG * AK_HALVES;
    float*  Mks = (float*)(Vss + NSTG * AK_HALVES);

    const int tid  = threadIdx.x;
    const int wid  = tid >> 5;
    const int lane = tid & 31;
    const int lr = lane >> 2;
    const int lc = lane & 3;
    const int wq = wid * 16;
    const int qt = blockIdx.x;
    const int h  = blockIdx.y;
    const int b  = blockIdx.z;

    const int a_row = (lane & 7) + ((lane >> 3) & 1) * 8;
    const int a_k   = (lane >> 4) * 8;
    const int b_row = (lane & 7) + (lane >> 4) * 8;
    const int b_k   = ((lane >> 3) & 1) * 8;

    const size_t qrow0 = (size_t)b * SEQ + (size_t)qt * 128;
    const __half* Qg = QKV + qrow0 * QKVD + h * DKH;
    const __half* Kb = QKV + (size_t)b * SEQ * QKVD + DMODEL + h * DKH;
    const __half* Vb = QKV + (size_t)b * SEQ * QKVD + 2 * DMODEL + h * DKH;
    const float* Mb = MF + (size_t)b * SEQ;

    // Q tile 128x64 (already scaled by 0.125*log2e in GEMM epilogue)
    {
        uint32_t qbase = smem_u32(Qs);
        #pragma unroll
        for (int t = 0; t < 4; t++) {
            int idx = tid + t * 256;
            int r = idx >> 3;
            int c = idx & 7;
            cp16(qbase + (uint32_t)(r * STR * 2 + c * 16),
                 Qg + (size_t)r * QKVD + c * 8);
        }
    }

    auto load_stage = [&](int s, int kt) {
        const __half* Kg = Kb + (size_t)kt * 64 * QKVD;
        const __half* Vg = Vb + (size_t)kt * 64 * QKVD;
        uint32_t kbase = smem_u32(Kss + s * AK_HALVES);
        uint32_t vbase = smem_u32(Vss + s * AK_HALVES);
        #pragma unroll
        for (int t = 0; t < 2; t++) {
            int idx = tid + t * 256;
            int r = idx >> 3;
            int c = idx & 7;
            uint32_t off = (uint32_t)(r * STR * 2 + c * 16);
            cp16(kbase + off, Kg + (size_t)r * QKVD + c * 8);
            cp16(vbase + off, Vg + (size_t)r * QKVD + c * 8);
        }
        if (tid < 16)
            cp16(smem_u32(Mks + s * 64) + tid * 16, Mb + kt * 64 + tid * 4);
        CP_COMMIT();
    };

    load_stage(0, 0);   // group 0 also carries the Q cp.asyncs
    load_stage(1, 1);
    load_stage(2, 2);

    float o[8][4];
    #pragma unroll
    for (int nt = 0; nt < 8; nt++)
        #pragma unroll
        for (int i = 0; i < 4; i++) o[nt][i] = 0.0f;
    float mst0 = -1e30f, mst1 = -1e30f, lst0 = 0.0f, lst1 = 0.0f;

    for (int kt = 0; kt < NTK; kt++) {
        int s = kt & 3;
        if (kt < NTK - 2)      asm volatile("cp.async.wait_group 2;" ::: "memory");
        else if (kt == NTK - 2) asm volatile("cp.async.wait_group 1;" ::: "memory");
        else                    asm volatile("cp.async.wait_group 0;" ::: "memory");
        __syncthreads();

        const __half* Kt = Kss + s * AK_HALVES;
        const __half* Vt = Vss + s * AK_HALVES;
        const float* mk = Mks + s * 64;

        // ---- scores: S = (Q*log2e/8) K^T ----
        float sa[8][4];
        #pragma unroll
        for (int nt = 0; nt < 8; nt++)
            #pragma unroll
            for (int i = 0; i < 4; i++) sa[nt][i] = 0.0f;

        #pragma unroll
        for (int ks = 0; ks < 4; ks++) {
            int k0 = ks * 16;
            uint32_t a[4];
            ldmx4(a, smem_u32(Qs + (wq + a_row) * STR + k0 + a_k));
            #pragma unroll
            for (int ntp = 0; ntp < 4; ntp++) {
                uint32_t bb[4];
                ldmx4(bb, smem_u32(Kt + (ntp * 16 + b_row) * STR + k0 + b_k));
                mma_f16(sa[2 * ntp],     a, &bb[0]);
                mma_f16(sa[2 * ntp + 1], a, &bb[2]);
            }
        }

        // ---- online softmax (log2 domain), P packed directly to A-frags ----
        float rm0 = -1e30f, rm1 = -1e30f;
        #pragma unroll
        for (int nt = 0; nt < 8; nt++) {
            float m0 = mk[nt * 8 + 2 * lc];
            float m1 = mk[nt * 8 + 2 * lc + 1];
            sa[nt][0] += m0; sa[nt][1] += m1;
            sa[nt][2] += m0; sa[nt][3] += m1;
            rm0 = fmaxf(rm0, fmaxf(sa[nt][0], sa[nt][1]));
            rm1 = fmaxf(rm1, fmaxf(sa[nt][2], sa[nt][3]));
        }
        rm0 = fmaxf(rm0, __shfl_xor_sync(0xffffffffu, rm0, 1));
        rm0 = fmaxf(rm0, __shfl_xor_sync(0xffffffffu, rm0, 2));
        rm1 = fmaxf(rm1, __shfl_xor_sync(0xffffffffu, rm1, 1));
        rm1 = fmaxf(rm1, __shfl_xor_sync(0xffffffffu, rm1, 2));

        float nm0 = fmaxf(mst0, rm0), nm1 = fmaxf(mst1, rm1);
        float al0 = exp2f(mst0 - nm0), al1 = exp2f(mst1 - nm1);
        mst0 = nm0; mst1 = nm1;

        uint32_t ph[8][2];
        float ps0 = 0.0f, ps1 = 0.0f;
        #pragma unroll
        for (int nt = 0; nt < 8; nt++) {
            float p0 = exp2f(sa[nt][0] - nm0);
            float p1 = exp2f(sa[nt][1] - nm0);
            float p2 = exp2f(sa[nt][2] - nm1);
            float p3 = exp2f(sa[nt][3] - nm1);
            ps0 += p0 + p1;
            ps1 += p2 + p3;
            ph[nt][0] = packh2(p0, p1);
            ph[nt][1] = packh2(p2, p3);
            o[nt][0] *= al0; o[nt][1] *= al0;
            o[nt][2] *= al1; o[nt][3] *= al1;
        }
        ps0 += __shfl_xor_sync(0xffffffffu, ps0, 1);
        ps0 += __shfl_xor_sync(0xffffffffu, ps0, 2);
        ps1 += __shfl_xor_sync(0xffffffffu, ps1, 1);
        ps1 += __shfl_xor_sync(0xffffffffu, ps1, 2);
        lst0 = lst0 * al0 + ps0;
        lst1 = lst1 * al1 + ps1;

        // ---- O += P V  (P from registers, V via ldmatrix.trans) ----
        #pragma unroll
        for (int ks = 0; ks < 4; ks++) {
            int k0 = ks * 16;
            uint32_t a[4] = { ph[2 * ks][0], ph[2 * ks][1],
                              ph[2 * ks + 1][0], ph[2 * ks + 1][1] };
            #pragma unroll
            for (int ntp = 0; ntp < 4; ntp++) {
                uint32_t bb[4];
                ldmx4t(bb, smem_u32(Vt + (k0 + a_row) * STR + ntp * 16 + a_k));
                mma_f16(o[2 * ntp],     a, &bb[0]);
                mma_f16(o[2 * ntp + 1], a, &bb[2]);
            }
        }

        if (kt + 3 < NTK) load_stage((kt + 3) & 3, kt + 3);
    }

    float inv0 = 1.0f / lst0;
    float inv1 = 1.0f / lst1;
    __half* Og = O + qrow0 * DMODEL + h * DKH;
    #pragma unroll
    for (int nt = 0; nt < 8; nt++) {
        int col = nt * 8 + 2 * lc;
        *(__half2*)(Og + (size_t)(wq + lr) * DMODEL + col) =
            __floats2half2_rn(o[nt][0] * inv0, o[nt][1] * inv0);
        *(__half2*)(Og + (size_t)(wq + lr + 8) * DMODEL + col) =
            __floats2half2_rn(o[nt][2] * inv1, o[nt][3] * inv1);
    }
}

// ---------------- launch ---------------------------------------------------
extern "C" void kernel_launch(void* const* d_in, const int* in_sizes, int n_in,
                              void* d_out, int out_size) {
    const float* X    = (const float*)d_in[0];
    const int*   mask = (const int*)d_in[1];
    const float* Wq   = (const float*)d_in[2];
    const float* Wk   = (const float*)d_in[3];
    const float* Wv   = (const float*)d_in[4];
    const float* Wo   = (const float*)d_in[5];
    float* out = (float*)d_out;

    __half *xh, *qkvh, *aoh, *wth;
    float *mf;
    cudaGetSymbolAddress((void**)&xh,   g_XH);
    cudaGetSymbolAddress((void**)&qkvh, g_QKVH);
    cudaGetSymbolAddress((void**)&aoh,  g_AOH);
    cudaGetSymbolAddress((void**)&wth,  g_WTH);
    cudaGetSymbolAddress((void**)&mf,   g_MF);

    cudaFuncSetAttribute(attn_mma_kernel,
                         cudaFuncAttributeMaxDynamicSharedMemorySize, ATTN_SMEM);
    cudaFuncSetAttribute(tgemm_h_kernel<0>,
                         cudaFuncAttributeMaxDynamicSharedMemorySize, TGEMM_SMEM);
    cudaFuncSetAttribute(tgemm_h_kernel<1>,
                         cudaFuncAttributeMaxDynamicSharedMemorySize, TGEMM_SMEM);

    maskprep_kernel<<<(BATCH*SEQ + 255) / 256, 256>>>(mask, mf);
    xtohalf_kernel<<<MTOT * DMODEL / 4 / 256, 256>>>(X, xh);
    transpose_kernel<<<dim3(32, 32, 4), dim3(32, 8)>>>(Wq, Wk, Wv, Wo, wth);

    // fused Q|K|V projection; Q columns pre-scaled by 0.125*log2e
    tgemm_h_kernel<1><<<dim3(QKVD / 128, MTOT / 128), 256, TGEMM_SMEM>>>(
        xh, wth, qkvh, QKVD, DMODEL, 0.125f * LOG2E);

    attn_mma_kernel<<<dim3(SEQ / 128, NHEAD, BATCH), 256, ATTN_SMEM>>>(qkvh, mf, aoh);

    tgemm_h_kernel<0><<<dim3(DMODEL / 128, MTOT / 128), 256, TGEMM_SMEM>>>(
        aoh, wth + 3 * DMODEL * DMODEL, out, DMODEL, 0, 1.0f);
}

// round 9
// speedup vs baseline: 7.4398x; 1.0252x over previous
#include <cuda_runtime.h>
#include <cuda_fp16.h>
#include <cstdint>

#define DMODEL 1024
#define NHEAD 16
#define DKH 64
#define BATCH 4
#define SEQ 2048
#define MTOT (BATCH*SEQ)   // 8192
#define QKVD (3*DMODEL)    // 3072
#define STR 72             // smem row stride in halves (144B = 9*16B)
#define LOG2E 1.4426950408889634f

// ---------------- scratch (static device globals; no allocation) ----------
__device__ __align__(16) __half g_XH[MTOT*DMODEL];
__device__ __align__(16) __half g_QKVH[MTOT*QKVD];
__device__ __align__(16) __half g_AOH[MTOT*DMODEL];
__device__ __align__(16) __half g_WTH[4*DMODEL*DMODEL];  // transposed [N,K] fp16
__device__ float g_MF[BATCH*SEQ];                        // additive mask (log2 domain)

// ---------------- helpers ---------------------------------------------------
__device__ __forceinline__ uint32_t smem_u32(const void* p) {
    uint32_t a;
    asm("{ .reg .u64 t; cvta.to.shared.u64 t, %1; cvt.u32.u64 %0, t; }"
        : "=r"(a) : "l"(p));
    return a;
}
__device__ __forceinline__ void cp16(uint32_t smem_addr, const void* gptr) {
    asm volatile("cp.async.cg.shared.global [%0], [%1], 16;"
                 :: "r"(smem_addr), "l"(gptr));
}
#define CP_COMMIT() asm volatile("cp.async.commit_group;" ::: "memory")

__device__ __forceinline__ void ldmx4(uint32_t* r, uint32_t addr) {
    asm volatile("ldmatrix.sync.aligned.m8n8.x4.shared.b16 {%0,%1,%2,%3}, [%4];"
        : "=r"(r[0]), "=r"(r[1]), "=r"(r[2]), "=r"(r[3]) : "r"(addr));
}
__device__ __forceinline__ void ldmx4t(uint32_t* r, uint32_t addr) {
    asm volatile("ldmatrix.sync.aligned.m8n8.x4.trans.shared.b16 {%0,%1,%2,%3}, [%4];"
        : "=r"(r[0]), "=r"(r[1]), "=r"(r[2]), "=r"(r[3]) : "r"(addr));
}
__device__ __forceinline__ void mma_f16(float* c, const uint32_t* a,
                                        const uint32_t* b) {
    asm volatile(
        "mma.sync.aligned.m16n8k16.row.col.f32.f16.f16.f32 "
        "{%0,%1,%2,%3}, {%4,%5,%6,%7}, {%8,%9}, {%0,%1,%2,%3};"
        : "+f"(c[0]), "+f"(c[1]), "+f"(c[2]), "+f"(c[3])
        : "r"(a[0]), "r"(a[1]), "r"(a[2]), "r"(a[3]), "r"(b[0]), "r"(b[1]));
}
__device__ __forceinline__ uint32_t packh2(float a, float b) {
    __half2 h = __floats2half2_rn(a, b);
    return *(uint32_t*)&h;
}
__device__ __forceinline__ uint32_t h2exp2(uint32_t x) {
    uint32_t r;
    asm("ex2.approx.f16x2 %0, %1;" : "=r"(r) : "r"(x));
    return r;
}

// ---------------- mask prep (log2 domain) -----------------------------------
__global__ void maskprep_kernel(const int* __restrict__ m, float* __restrict__ mf) {
    int i = blockIdx.x * 256 + threadIdx.x;
    if (i < BATCH * SEQ) mf[i] = (1.0f - (float)m[i]) * (-1e9f * LOG2E);
}

// ---------------- X fp32 -> fp16 -------------------------------------------
__global__ __launch_bounds__(256) void xtohalf_kernel(
        const float* __restrict__ in, __half* __restrict__ out)
{
    int i = blockIdx.x * 256 + threadIdx.x;
    float4 v = ((const float4*)in)[i];
    ((__half2*)out)[2*i]   = __floats2half2_rn(v.x, v.y);
    ((__half2*)out)[2*i+1] = __floats2half2_rn(v.z, v.w);
}

// ---------------- fused transpose [K,N]->[N,K] + fp16 ----------------------
__global__ __launch_bounds__(256) void transpose_kernel(
        const float* __restrict__ Wq, const float* __restrict__ Wk,
        const float* __restrict__ Wv, const float* __restrict__ Wo,
        __half* __restrict__ wt)
{
    __shared__ float t[32][33];
    int z = blockIdx.z;
    const float* in = (z == 0) ? Wq : (z == 1) ? Wk : (z == 2) ? Wv : Wo;
    __half* out = wt + (size_t)z * DMODEL * DMODEL;
    int x = blockIdx.x * 32 + threadIdx.x;
    int y = blockIdx.y * 32 + threadIdx.y;
    #pragma unroll
    for (int j = 0; j < 32; j += 8)
        t[threadIdx.y + j][threadIdx.x] = in[(size_t)(y + j) * DMODEL + x];
    __syncthreads();
    x = blockIdx.y * 32 + threadIdx.x;
    y = blockIdx.x * 32 + threadIdx.y;
    #pragma unroll
    for (int j = 0; j < 32; j += 8)
        out[(size_t)(y + j) * DMODEL + x] =
            __float2half_rn(t[threadIdx.x][threadIdx.y + j]);
}

// ---------------- fp16 mma GEMM: C[M,N] = A[M,K] @ Bt[N,K]^T ----------------
#define NKT2 (DMODEL/64)
#define STAGE_BYTES (2*128*STR*2)
#define TGEMM_SMEM (3*STAGE_BYTES)

template<int HOUT>
__global__ __launch_bounds__(256, 2) void tgemm_h_kernel(
        const __half* __restrict__ A, const __half* __restrict__ Bt,
        void* __restrict__ Cv, int N, int qcols, float qscale)
{
    extern __shared__ char smb[];
    const int tid  = threadIdx.x;
    const int lane = tid & 31;
    const int wid  = tid >> 5;
    const int bm = blockIdx.y * 128;
    const int bn = blockIdx.x * 128;
    const int wm = (wid & 1) * 64;
    const int wn = (wid >> 1) * 32;
    const int K = DMODEL;

    float acc[4][4][4];
    #pragma unroll
    for (int mt = 0; mt < 4; mt++)
        #pragma unroll
        for (int nt = 0; nt < 4; nt++)
            #pragma unroll
            for (int i = 0; i < 4; i++) acc[mt][nt][i] = 0.0f;

    const __half* gA = A  + (size_t)bm * K;
    const __half* gB = Bt + (size_t)bn * K;

    auto load_stage = [&](int s, int kt) {
        uint32_t base  = smem_u32(smb) + s * STAGE_BYTES;
        uint32_t baseB = base + 128 * STR * 2;
        const __half* pa = gA + kt * 64;
        const __half* pb = gB + kt * 64;
        #pragma unroll
        for (int i = 0; i < 4; i++) {
            int idx = tid + i * 256;
            int r = idx >> 3;
            int c = idx & 7;
            uint32_t off = (uint32_t)(r * STR * 2 + c * 16);
            cp16(base  + off, pa + (size_t)r * K + c * 8);
            cp16(baseB + off, pb + (size_t)r * K + c * 8);
        }
        CP_COMMIT();
    };

    load_stage(0, 0);
    load_stage(1, 1);

    const int lr = lane >> 2;
    const int lc = lane & 3;
    const int a_row = (lane & 7) + ((lane >> 3) & 1) * 8;
    const int a_k   = (lane >> 4) * 8;
    const int b_row = (lane & 7) + (lane >> 4) * 8;
    const int b_k   = ((lane >> 3) & 1) * 8;

    for (int kt = 0; kt < NKT2; kt++) {
        int s = kt % 3;
        if (kt < NKT2 - 1) asm volatile("cp.async.wait_group 1;" ::: "memory");
        else               asm volatile("cp.async.wait_group 0;" ::: "memory");
        __syncthreads();

        const __half* As = (const __half*)(smb + s * STAGE_BYTES);
        const __half* Bs = As + 128 * STR;

        #pragma unroll
        for (int ks = 0; ks < 4; ks++) {
            int k0 = ks * 16;
            uint32_t a[4][4], b[2][4];
            #pragma unroll
            for (int mt = 0; mt < 4; mt++)
                ldmx4(a[mt], smem_u32(As + (wm + mt * 16 + a_row) * STR + k0 + a_k));
            #pragma unroll
            for (int ntp = 0; ntp < 2; ntp++)
                ldmx4(b[ntp], smem_u32(Bs + (wn + ntp * 16 + b_row) * STR + k0 + b_k));
            #pragma unroll
            for (int mt = 0; mt < 4; mt++) {
                mma_f16(acc[mt][0], a[mt], &b[0][0]);
                mma_f16(acc[mt][1], a[mt], &b[0][2]);
                mma_f16(acc[mt][2], a[mt], &b[1][0]);
                mma_f16(acc[mt][3], a[mt], &b[1][2]);
            }
        }
        if (kt + 2 < NKT2) load_stage((kt + 2) % 3, kt + 2);
    }

    const float sc = (bn < qcols) ? qscale : 1.0f;
    #pragma unroll
    for (int mt = 0; mt < 4; mt++) {
        int row = bm + wm + mt * 16 + lr;
        #pragma unroll
        for (int nt = 0; nt < 4; nt++) {
            int col = bn + wn + nt * 8 + 2 * lc;
            float c0 = acc[mt][nt][0] * sc, c1 = acc[mt][nt][1] * sc;
            float c2 = acc[mt][nt][2] * sc, c3 = acc[mt][nt][3] * sc;
            if (HOUT) {
                __half* C = (__half*)Cv;
                *(__half2*)(C + (size_t)row * N + col) = __floats2half2_rn(c0, c1);
                *(__half2*)(C + (size_t)(row + 8) * N + col) = __floats2half2_rn(c2, c3);
            } else {
                float* C = (float*)Cv;
                *(float2*)(C + (size_t)row * N + col) = make_float2(c0, c1);
                *(float2*)(C + (size_t)(row + 8) * N + col) = make_float2(c2, c3);
            }
        }
    }
}

// ---------------- fp16 mma flash attention ---------------------------------
// 256 thr / 8 warps; 128 q x 64 k per iter; 4-stage K/V; P in regs;
// P row-sum via ones-B MMA; exp via ex2.approx.f16x2.
#define NTK (SEQ/64)
#define NSTG 4
#define AQ_HALVES (128*STR)
#define AK_HALVES (64*STR)
#define ATTN_SMEM ((AQ_HALVES + NSTG*2*AK_HALVES)*2 + NSTG*64*(int)sizeof(float))

__global__ __launch_bounds__(256, 2) void attn_mma_kernel(
        const __half* __restrict__ QKV, const float* __restrict__ MF,
        __half* __restrict__ O)
{
    extern __shared__ char smb[];
    __half* Qs  = (__half*)smb;
    __half* Kss = Qs + AQ_HALVES;
    __half* Vss = Kss + NSTG * AK_HALVES;
    float*  Mks = (float*)(Vss + NSTG * AK_HALVES);

    const int tid  = threadIdx.x;
    const int wid  = tid >> 5;
    const int lane = tid & 31;
    const int lr = lane >> 2;
    const int lc = lane & 3;
    const int wq = wid * 16;
    const int qt = blockIdx.x;
    const int h  = blockIdx.y;
    const int b  = blockIdx.z;

    const int a_row = (lane & 7) + ((lane >> 3) & 1) * 8;
    const int a_k   = (lane >> 4) * 8;
    const int b_row = (lane & 7) + (lane >> 4) * 8;
    const int b_k   = ((lane >> 3) & 1) * 8;

    const size_t qrow0 = (size_t)b * SEQ + (size_t)qt * 128;
    const __half* Qg = QKV + qrow0 * QKVD + h * DKH;
    const __half* Kb = QKV + (size_t)b * SEQ * QKVD + DMODEL + h * DKH;
    const __half* Vb = QKV + (size_t)b * SEQ * QKVD + 2 * DMODEL + h * DKH;
    const float* Mb = MF + (size_t)b * SEQ;

    // Q tile 128x64 (pre-scaled by 0.125*log2e in GEMM epilogue)
    {
        uint32_t qbase = smem_u32(Qs);
        #pragma unroll
        for (int t = 0; t < 4; t++) {
            int idx = tid + t * 256;
            int r = idx >> 3;
            int c = idx & 7;
            cp16(qbase + (uint32_t)(r * STR * 2 + c * 16),
                 Qg + (size_t)r * QKVD + c * 8);
        }
    }

    auto load_stage = [&](int s, int kt) {
        const __half* Kg = Kb + (size_t)kt * 64 * QKVD;
        const __half* Vg = Vb + (size_t)kt * 64 * QKVD;
        uint32_t kbase = smem_u32(Kss + s * AK_HALVES);
        uint32_t vbase = smem_u32(Vss + s * AK_HALVES);
        #pragma unroll
        for (int t = 0; t < 2; t++) {
            int idx = tid + t * 256;
            int r = idx >> 3;
            int c = idx & 7;
            uint32_t off = (uint32_t)(r * STR * 2 + c * 16);
            cp16(kbase + off, Kg + (size_t)r * QKVD + c * 8);
            cp16(vbase + off, Vg + (size_t)r * QKVD + c * 8);
        }
        if (tid < 16)
            cp16(smem_u32(Mks + s * 64) + tid * 16, Mb + kt * 64 + tid * 4);
        CP_COMMIT();
    };

    load_stage(0, 0);
    load_stage(1, 1);
    load_stage(2, 2);

    float o[8][4];
    #pragma unroll
    for (int nt = 0; nt < 8; nt++)
        #pragma unroll
        for (int i = 0; i < 4; i++) o[nt][i] = 0.0f;
    float mst0 = -1e30f, mst1 = -1e30f, lst0 = 0.0f, lst1 = 0.0f;

    const uint32_t ones2 = packh2(1.0f, 1.0f);
    const uint32_t bones[2] = { ones2, ones2 };

    for (int kt = 0; kt < NTK; kt++) {
        int s = kt & 3;
        if (kt < NTK - 2)       asm volatile("cp.async.wait_group 2;" ::: "memory");
        else if (kt == NTK - 2) asm volatile("cp.async.wait_group 1;" ::: "memory");
        else                    asm volatile("cp.async.wait_group 0;" ::: "memory");
        __syncthreads();

        const __half* Kt = Kss + s * AK_HALVES;
        const __half* Vt = Vss + s * AK_HALVES;
        const float* mk = Mks + s * 64;

        // ---- scores: S = (Q*log2e/8) K^T ----
        float sa[8][4];
        #pragma unroll
        for (int nt = 0; nt < 8; nt++)
            #pragma unroll
            for (int i = 0; i < 4; i++) sa[nt][i] = 0.0f;

        #pragma unroll
        for (int ks = 0; ks < 4; ks++) {
            int k0 = ks * 16;
            uint32_t a[4];
            ldmx4(a, smem_u32(Qs + (wq + a_row) * STR + k0 + a_k));
            #pragma unroll
            for (int ntp = 0; ntp < 4; ntp++) {
                uint32_t bb[4];
                ldmx4(bb, smem_u32(Kt + (ntp * 16 + b_row) * STR + k0 + b_k));
                mma_f16(sa[2 * ntp],     a, &bb[0]);
                mma_f16(sa[2 * ntp + 1], a, &bb[2]);
            }
        }

        // ---- online softmax (log2 domain) ----
        float rm0 = -1e30f, rm1 = -1e30f;
        #pragma unroll
        for (int nt = 0; nt < 8; nt++) {
            float2 m = *(const float2*)(mk + nt * 8 + 2 * lc);
            sa[nt][0] += m.x; sa[nt][1] += m.y;
            sa[nt][2] += m.x; sa[nt][3] += m.y;
            rm0 = fmaxf(rm0, fmaxf(sa[nt][0], sa[nt][1]));
            rm1 = fmaxf(rm1, fmaxf(sa[nt][2], sa[nt][3]));
        }
        rm0 = fmaxf(rm0, __shfl_xor_sync(0xffffffffu, rm0, 1));
        rm0 = fmaxf(rm0, __shfl_xor_sync(0xffffffffu, rm0, 2));
        rm1 = fmaxf(rm1, __shfl_xor_sync(0xffffffffu, rm1, 1));
        rm1 = fmaxf(rm1, __shfl_xor_sync(0xffffffffu, rm1, 2));

        float nm0 = fmaxf(mst0, rm0), nm1 = fmaxf(mst1, rm1);
        float al0 = exp2f(mst0 - nm0), al1 = exp2f(mst1 - nm1);
        mst0 = nm0; mst1 = nm1;

        // P = 2^(s-m) computed pairwise in fp16 (ex2.approx.f16x2)
        uint32_t ph[8][2];
        #pragma unroll
        for (int nt = 0; nt < 8; nt++) {
            ph[nt][0] = h2exp2(packh2(sa[nt][0] - nm0, sa[nt][1] - nm0));
            ph[nt][1] = h2exp2(packh2(sa[nt][2] - nm1, sa[nt][3] - nm1));
            o[nt][0] *= al0; o[nt][1] *= al0;
            o[nt][2] *= al1; o[nt][3] *= al1;
        }

        // ---- O += P V ; row-sum(P) via ones-B MMA ----
        float lacc[4] = {0.0f, 0.0f, 0.0f, 0.0f};
        #pragma unroll
        for (int ks = 0; ks < 4; ks++) {
            int k0 = ks * 16;
            uint32_t a[4] = { ph[2 * ks][0], ph[2 * ks][1],
                              ph[2 * ks + 1][0], ph[2 * ks + 1][1] };
            #pragma unroll
            for (int ntp = 0; ntp < 4; ntp++) {
                uint32_t bb[4];
                ldmx4t(bb, smem_u32(Vt + (k0 + a_row) * STR + ntp * 16 + a_k));
                mma_f16(o[2 * ntp],     a, &bb[0]);
                mma_f16(o[2 * ntp + 1], a, &bb[2]);
            }
            mma_f16(lacc, a, bones);
        }
        lst0 = lst0 * al0 + lacc[0];
        lst1 = lst1 * al1 + lacc[2];

        if (kt + 3 < NTK) load_stage((kt + 3) & 3, kt + 3);
    }

    float inv0 = 1.0f / lst0;
    float inv1 = 1.0f / lst1;
    __half* Og = O + qrow0 * DMODEL + h * DKH;
    #pragma unroll
    for (int nt = 0; nt < 8; nt++) {
        int col = nt * 8 + 2 * lc;
        *(__half2*)(Og + (size_t)(wq + lr) * DMODEL + col) =
            __floats2half2_rn(o[nt][0] * inv0, o[nt][1] * inv0);
        *(__half2*)(Og + (size_t)(wq + lr + 8) * DMODEL + col) =
            __floats2half2_rn(o[nt][2] * inv1, o[nt][3] * inv1);
    }
}

// ---------------- launch ---------------------------------------------------
extern "C" void kernel_launch(void* const* d_in, const int* in_sizes, int n_in,
                              void* d_out, int out_size) {
    const float* X    = (const float*)d_in[0];
    const int*   mask = (const int*)d_in[1];
    const float* Wq   = (const float*)d_in[2];
    const float* Wk   = (const float*)d_in[3];
    const float* Wv   = (const float*)d_in[4];
    const float* Wo   = (const float*)d_in[5];
    float* out = (float*)d_out;

    __half *xh, *qkvh, *aoh, *wth;
    float *mf;
    cudaGetSymbolAddress((void**)&xh,   g_XH);
    cudaGetSymbolAddress((void**)&qkvh, g_QKVH);
    cudaGetSymbolAddress((void**)&aoh,  g_AOH);
    cudaGetSymbolAddress((void**)&wth,  g_WTH);
    cudaGetSymbolAddress((void**)&mf,   g_MF);

    cudaFuncSetAttribute(attn_mma_kernel,
                         cudaFuncAttributeMaxDynamicSharedMemorySize, ATTN_SMEM);
    cudaFuncSetAttribute(tgemm_h_kernel<0>,
                         cudaFuncAttributeMaxDynamicSharedMemorySize, TGEMM_SMEM);
    cudaFuncSetAttribute(tgemm_h_kernel<1>,
                         cudaFuncAttributeMaxDynamicSharedMemorySize, TGEMM_SMEM);

    maskprep_kernel<<<(BATCH*SEQ + 255) / 256, 256>>>(mask, mf);
    xtohalf_kernel<<<MTOT * DMODEL / 4 / 256, 256>>>(X, xh);
    transpose_kernel<<<dim3(32, 32, 4), dim3(32, 8)>>>(Wq, Wk, Wv, Wo, wth);

    tgemm_h_kernel<1><<<dim3(QKVD / 128, MTOT / 128), 256, TGEMM_SMEM>>>(
        xh, wth, qkvh, QKVD, DMODEL, 0.125f * LOG2E);

    attn_mma_kernel<<<dim3(SEQ / 128, NHEAD, BATCH), 256, ATTN_SMEM>>>(qkvh, mf, aoh);

    tgemm_h_kernel<0><<<dim3(DMODEL / 128, MTOT / 128), 256, TGEMM_SMEM>>>(
        aoh, wth + 3 * DMODEL * DMODEL, out, DMODEL, 0, 1.0f);
}

// round 11
// speedup vs baseline: 7.6787x; 1.0321x over previous
#include <cuda_runtime.h>
#include <cuda_fp16.h>
#include <cstdint>

#define DMODEL 1024
#define NHEAD 16
#define DKH 64
#define BATCH 4
#define SEQ 2048
#define MTOT (BATCH*SEQ)   // 8192
#define QKVD (3*DMODEL)    // 3072
#define STR 72             // smem row stride in halves (144B = 9*16B)
#define LOG2E 1.4426950408889634f

// ---------------- scratch (static device globals; no allocation) ----------
__device__ __align__(16) __half g_XH[MTOT*DMODEL];
__device__ __align__(16) __half g_QKVH[MTOT*QKVD];
__device__ __align__(16) __half g_AOH[MTOT*DMODEL];
__device__ __align__(16) __half g_WTH[4*DMODEL*DMODEL];  // transposed [N,K] fp16
__device__ float g_MF[BATCH*SEQ];                        // additive mask (log2 domain)

// ---------------- helpers ---------------------------------------------------
__device__ __forceinline__ uint32_t smem_u32(const void* p) {
    uint32_t a;
    asm("{ .reg .u64 t; cvta.to.shared.u64 t, %1; cvt.u32.u64 %0, t; }"
        : "=r"(a) : "l"(p));
    return a;
}
__device__ __forceinline__ void cp16(uint32_t smem_addr, const void* gptr) {
    asm volatile("cp.async.cg.shared.global [%0], [%1], 16;"
                 :: "r"(smem_addr), "l"(gptr));
}
#define CP_COMMIT() asm volatile("cp.async.commit_group;" ::: "memory")

__device__ __forceinline__ void ldmx4(uint32_t* r, uint32_t addr) {
    asm volatile("ldmatrix.sync.aligned.m8n8.x4.shared.b16 {%0,%1,%2,%3}, [%4];"
        : "=r"(r[0]), "=r"(r[1]), "=r"(r[2]), "=r"(r[3]) : "r"(addr));
}
__device__ __forceinline__ void ldmx4t(uint32_t* r, uint32_t addr) {
    asm volatile("ldmatrix.sync.aligned.m8n8.x4.trans.shared.b16 {%0,%1,%2,%3}, [%4];"
        : "=r"(r[0]), "=r"(r[1]), "=r"(r[2]), "=r"(r[3]) : "r"(addr));
}
__device__ __forceinline__ void mma_f16(float* c, const uint32_t* a,
                                        const uint32_t* b) {
    asm volatile(
        "mma.sync.aligned.m16n8k16.row.col.f32.f16.f16.f32 "
        "{%0,%1,%2,%3}, {%4,%5,%6,%7}, {%8,%9}, {%0,%1,%2,%3};"
        : "+f"(c[0]), "+f"(c[1]), "+f"(c[2]), "+f"(c[3])
        : "r"(a[0]), "r"(a[1]), "r"(a[2]), "r"(a[3]), "r"(b[0]), "r"(b[1]));
}
__device__ __forceinline__ uint32_t packh2(float a, float b) {
    __half2 h = __floats2half2_rn(a, b);
    return *(uint32_t*)&h;
}
__device__ __forceinline__ uint32_t h2exp2(uint32_t x) {
    uint32_t r;
    asm("ex2.approx.f16x2 %0, %1;" : "=r"(r) : "r"(x));
    return r;
}

// ---------------- mask prep (log2 domain) -----------------------------------
__global__ void maskprep_kernel(const int* __restrict__ m, float* __restrict__ mf) {
    int i = blockIdx.x * 256 + threadIdx.x;
    if (i < BATCH * SEQ) mf[i] = (1.0f - (float)m[i]) * (-1e9f * LOG2E);
}

// ---------------- X fp32 -> fp16 -------------------------------------------
__global__ __launch_bounds__(256) void xtohalf_kernel(
        const float* __restrict__ in, __half* __restrict__ out)
{
    int i = blockIdx.x * 256 + threadIdx.x;
    float4 v = ((const float4*)in)[i];
    ((__half2*)out)[2*i]   = __floats2half2_rn(v.x, v.y);
    ((__half2*)out)[2*i+1] = __floats2half2_rn(v.z, v.w);
}

// ---------------- fused transpose [K,N]->[N,K] + fp16 ----------------------
__global__ __launch_bounds__(256) void transpose_kernel(
        const float* __restrict__ Wq, const float* __restrict__ Wk,
        const float* __restrict__ Wv, const float* __restrict__ Wo,
        __half* __restrict__ wt)
{
    __shared__ float t[32][33];
    int z = blockIdx.z;
    const float* in = (z == 0) ? Wq : (z == 1) ? Wk : (z == 2) ? Wv : Wo;
    __half* out = wt + (size_t)z * DMODEL * DMODEL;
    int x = blockIdx.x * 32 + threadIdx.x;
    int y = blockIdx.y * 32 + threadIdx.y;
    #pragma unroll
    for (int j = 0; j < 32; j += 8)
        t[threadIdx.y + j][threadIdx.x] = in[(size_t)(y + j) * DMODEL + x];
    __syncthreads();
    x = blockIdx.y * 32 + threadIdx.x;
    y = blockIdx.x * 32 + threadIdx.y;
    #pragma unroll
    for (int j = 0; j < 32; j += 8)
        out[(size_t)(y + j) * DMODEL + x] =
            __float2half_rn(t[threadIdx.x][threadIdx.y + j]);
}

// ---------------- fp16 mma GEMM: C[M,N] = A[M,K] @ Bt[N,K]^T ----------------
#define NKT2 (DMODEL/64)
#define STAGE_BYTES (2*128*STR*2)
#define TGEMM_SMEM (3*STAGE_BYTES)

template<int HOUT>
__global__ __launch_bounds__(256, 2) void tgemm_h_kernel(
        const __half* __restrict__ A, const __half* __restrict__ Bt,
        void* __restrict__ Cv, int N, int qcols, float qscale)
{
    extern __shared__ char smb[];
    const int tid  = threadIdx.x;
    const int lane = tid & 31;
    const int wid  = tid >> 5;
    const int bm = blockIdx.y * 128;
    const int bn = blockIdx.x * 128;
    const int wm = (wid & 1) * 64;
    const int wn = (wid >> 1) * 32;
    const int K = DMODEL;

    float acc[4][4][4];
    #pragma unroll
    for (int mt = 0; mt < 4; mt++)
        #pragma unroll
        for (int nt = 0; nt < 4; nt++)
            #pragma unroll
            for (int i = 0; i < 4; i++) acc[mt][nt][i] = 0.0f;

    const __half* gA = A  + (size_t)bm * K;
    const __half* gB = Bt + (size_t)bn * K;

    auto load_stage = [&](int s, int kt) {
        uint32_t base  = smem_u32(smb) + s * STAGE_BYTES;
        uint32_t baseB = base + 128 * STR * 2;
        const __half* pa = gA + kt * 64;
        const __half* pb = gB + kt * 64;
        #pragma unroll
        for (int i = 0; i < 4; i++) {
            int idx = tid + i * 256;
            int r = idx >> 3;
            int c = idx & 7;
            uint32_t off = (uint32_t)(r * STR * 2 + c * 16);
            cp16(base  + off, pa + (size_t)r * K + c * 8);
            cp16(baseB + off, pb + (size_t)r * K + c * 8);
        }
        CP_COMMIT();
    };

    load_stage(0, 0);
    load_stage(1, 1);

    const int lr = lane >> 2;
    const int lc = lane & 3;
    const int a_row = (lane & 7) + ((lane >> 3) & 1) * 8;
    const int a_k   = (lane >> 4) * 8;
    const int b_row = (lane & 7) + (lane >> 4) * 8;
    const int b_k   = ((lane >> 3) & 1) * 8;

    #pragma unroll 3
    for (int kt = 0; kt < NKT2; kt++) {
        int s = kt % 3;
        if (kt < NKT2 - 1) asm volatile("cp.async.wait_group 1;" ::: "memory");
        else               asm volatile("cp.async.wait_group 0;" ::: "memory");
        __syncthreads();

        const __half* As = (const __half*)(smb + s * STAGE_BYTES);
        const __half* Bs = As + 128 * STR;

        #pragma unroll
        for (int ks = 0; ks < 4; ks++) {
            int k0 = ks * 16;
            uint32_t a[4][4], b[2][4];
            #pragma unroll
            for (int mt = 0; mt < 4; mt++)
                ldmx4(a[mt], smem_u32(As + (wm + mt * 16 + a_row) * STR + k0 + a_k));
            #pragma unroll
            for (int ntp = 0; ntp < 2; ntp++)
                ldmx4(b[ntp], smem_u32(Bs + (wn + ntp * 16 + b_row) * STR + k0 + b_k));
            #pragma unroll
            for (int mt = 0; mt < 4; mt++) {
                mma_f16(acc[mt][0], a[mt], &b[0][0]);
                mma_f16(acc[mt][1], a[mt], &b[0][2]);
                mma_f16(acc[mt][2], a[mt], &b[1][0]);
                mma_f16(acc[mt][3], a[mt], &b[1][2]);
            }
        }
        if (kt + 2 < NKT2) load_stage((kt + 2) % 3, kt + 2);
    }

    const float sc = (bn < qcols) ? qscale : 1.0f;
    #pragma unroll
    for (int mt = 0; mt < 4; mt++) {
        int row = bm + wm + mt * 16 + lr;
        #pragma unroll
        for (int nt = 0; nt < 4; nt++) {
            int col = bn + wn + nt * 8 + 2 * lc;
            float c0 = acc[mt][nt][0] * sc, c1 = acc[mt][nt][1] * sc;
            float c2 = acc[mt][nt][2] * sc, c3 = acc[mt][nt][3] * sc;
            if (HOUT) {
                __half* C = (__half*)Cv;
                *(__half2*)(C + (size_t)row * N + col) = __floats2half2_rn(c0, c1);
                *(__half2*)(C + (size_t)(row + 8) * N + col) = __floats2half2_rn(c2, c3);
            } else {
                float* C = (float*)Cv;
                *(float2*)(C + (size_t)row * N + col) = make_float2(c0, c1);
                *(float2*)(C + (size_t)(row + 8) * N + col) = make_float2(c2, c3);
            }
        }
    }
}

// ---------------- fp16 mma flash attention (online softmax) -----------------
// 256 thr / 8 warps; 128 q x 64 k per iter; 4-stage K/V; P in regs;
// l via ones-B MMA; exp via ex2.approx.f16x2; Q fragments hoisted.
#define NTK (SEQ/64)
#define NSTG 4
#define AQ_HALVES (128*STR)
#define AK_HALVES (64*STR)
#define ATTN_SMEM ((AQ_HALVES + NSTG*2*AK_HALVES)*2 + NSTG*64*(int)sizeof(float))

__global__ __launch_bounds__(256, 2) void attn_mma_kernel(
        const __half* __restrict__ QKV, const float* __restrict__ MF,
        __half* __restrict__ O)
{
    extern __shared__ char smb[];
    __half* Qs  = (__half*)smb;
    __half* Kss = Qs + AQ_HALVES;
    __half* Vss = Kss + NSTG * AK_HALVES;
    float*  Mks = (float*)(Vss + NSTG * AK_HALVES);

    const int tid  = threadIdx.x;
    const int wid  = tid >> 5;
    const int lane = tid & 31;
    const int lr = lane >> 2;
    const int lc = lane & 3;
    const int wq = wid * 16;
    const int qt = blockIdx.x;
    const int h  = blockIdx.y;
    const int b  = blockIdx.z;

    const int a_row = (lane & 7) + ((lane >> 3) & 1) * 8;
    const int a_k   = (lane >> 4) * 8;
    const int b_row = (lane & 7) + (lane >> 4) * 8;
    const int b_k   = ((lane >> 3) & 1) * 8;

    const size_t qrow0 = (size_t)b * SEQ + (size_t)qt * 128;
    const __half* Qg = QKV + qrow0 * QKVD + h * DKH;
    const __half* Kb = QKV + (size_t)b * SEQ * QKVD + DMODEL + h * DKH;
    const __half* Vb = QKV + (size_t)b * SEQ * QKVD + 2 * DMODEL + h * DKH;
    const float* Mb = MF + (size_t)b * SEQ;

    // Q tile (pre-scaled by 0.125*log2e in GEMM epilogue), in cp.async group 0
    {
        uint32_t qbase = smem_u32(Qs);
        #pragma unroll
        for (int t = 0; t < 4; t++) {
            int idx = tid + t * 256;
            int r = idx >> 3;
            int c = idx & 7;
            cp16(qbase + (uint32_t)(r * STR * 2 + c * 16),
                 Qg + (size_t)r * QKVD + c * 8);
        }
    }

    auto load_stage = [&](int s, int kt) {
        const __half* Kg = Kb + (size_t)kt * 64 * QKVD;
        const __half* Vg = Vb + (size_t)kt * 64 * QKVD;
        uint32_t kbase = smem_u32(Kss + s * AK_HALVES);
        uint32_t vbase = smem_u32(Vss + s * AK_HALVES);
        #pragma unroll
        for (int t = 0; t < 2; t++) {
            int idx = tid + t * 256;
            int r = idx >> 3;
            int c = idx & 7;
            uint32_t off = (uint32_t)(r * STR * 2 + c * 16);
            cp16(kbase + off, Kg + (size_t)r * QKVD + c * 8);
            cp16(vbase + off, Vg + (size_t)r * QKVD + c * 8);
        }
        if (tid < 16)
            cp16(smem_u32(Mks + s * 64) + tid * 16, Mb + kt * 64 + tid * 4);
        CP_COMMIT();
    };

    load_stage(0, 0);   // group 0 also carries the Q cp.asyncs
    load_stage(1, 1);
    load_stage(2, 2);

    // wait for Q (group 0) and hoist Q fragments into registers
    asm volatile("cp.async.wait_group 2;" ::: "memory");
    __syncthreads();
    uint32_t qf[4][4];
    #pragma unroll
    for (int ks = 0; ks < 4; ks++)
        ldmx4(qf[ks], smem_u32(Qs + (wq + a_row) * STR + ks * 16 + a_k));

    float o[8][4];
    #pragma unroll
    for (int nt = 0; nt < 8; nt++)
        #pragma unroll
        for (int i = 0; i < 4; i++) o[nt][i] = 0.0f;
    float mst0 = -1e30f, mst1 = -1e30f, lst0 = 0.0f, lst1 = 0.0f;

    const uint32_t ones2 = packh2(1.0f, 1.0f);
    const uint32_t bones[2] = { ones2, ones2 };

    #pragma unroll 4
    for (int kt = 0; kt < NTK; kt++) {
        int s = kt & 3;
        if (kt < NTK - 2)       asm volatile("cp.async.wait_group 2;" ::: "memory");
        else if (kt == NTK - 2) asm volatile("cp.async.wait_group 1;" ::: "memory");
        else                    asm volatile("cp.async.wait_group 0;" ::: "memory");
        __syncthreads();

        const __half* Kt = Kss + s * AK_HALVES;
        const __half* Vt = Vss + s * AK_HALVES;
        const float* mk = Mks + s * 64;

        // ---- scores: S = (Q*log2e/8) K^T ----
        float sa[8][4];
        #pragma unroll
        for (int nt = 0; nt < 8; nt++)
            #pragma unroll
            for (int i = 0; i < 4; i++) sa[nt][i] = 0.0f;

        #pragma unroll
        for (int ks = 0; ks < 4; ks++) {
            int k0 = ks * 16;
            #pragma unroll
            for (int ntp = 0; ntp < 4; ntp++) {
                uint32_t bb[4];
                ldmx4(bb, smem_u32(Kt + (ntp * 16 + b_row) * STR + k0 + b_k));
                mma_f16(sa[2 * ntp],     qf[ks], &bb[0]);
                mma_f16(sa[2 * ntp + 1], qf[ks], &bb[2]);
            }
        }

        // ---- online softmax (log2 domain) ----
        float rm0 = -1e30f, rm1 = -1e30f;
        #pragma unroll
        for (int nt = 0; nt < 8; nt++) {
            float2 m = *(const float2*)(mk + nt * 8 + 2 * lc);
            sa[nt][0] += m.x; sa[nt][1] += m.y;
            sa[nt][2] += m.x; sa[nt][3] += m.y;
            rm0 = fmaxf(rm0, fmaxf(sa[nt][0], sa[nt][1]));
            rm1 = fmaxf(rm1, fmaxf(sa[nt][2], sa[nt][3]));
        }
        rm0 = fmaxf(rm0, __shfl_xor_sync(0xffffffffu, rm0, 1));
        rm0 = fmaxf(rm0, __shfl_xor_sync(0xffffffffu, rm0, 2));
        rm1 = fmaxf(rm1, __shfl_xor_sync(0xffffffffu, rm1, 1));
        rm1 = fmaxf(rm1, __shfl_xor_sync(0xffffffffu, rm1, 2));

        float nm0 = fmaxf(mst0, rm0), nm1 = fmaxf(mst1, rm1);
        float al0 = exp2f(mst0 - nm0), al1 = exp2f(mst1 - nm1);
        mst0 = nm0; mst1 = nm1;

        // P = 2^(s-m) pairwise in fp16 (ex2.approx.f16x2)
        uint32_t ph[8][2];
        #pragma unroll
        for (int nt = 0; nt < 8; nt++) {
            ph[nt][0] = h2exp2(packh2(sa[nt][0] - nm0, sa[nt][1] - nm0));
            ph[nt][1] = h2exp2(packh2(sa[nt][2] - nm1, sa[nt][3] - nm1));
            o[nt][0] *= al0; o[nt][1] *= al0;
            o[nt][2] *= al1; o[nt][3] *= al1;
        }

        // ---- O += P V ; row-sum(P) via ones-B MMA ----
        float lacc[4] = {0.0f, 0.0f, 0.0f, 0.0f};
        #pragma unroll
        for (int ks = 0; ks < 4; ks++) {
            int k0 = ks * 16;
            uint32_t a[4] = { ph[2 * ks][0], ph[2 * ks][1],
                              ph[2 * ks + 1][0], ph[2 * ks + 1][1] };
            #pragma unroll
            for (int ntp = 0; ntp < 4; ntp++) {
                uint32_t bb[4];
                ldmx4t(bb, smem_u32(Vt + (k0 + a_row) * STR + ntp * 16 + a_k));
                mma_f16(o[2 * ntp],     a, &bb[0]);
                mma_f16(o[2 * ntp + 1], a, &bb[2]);
            }
            mma_f16(lacc, a, bones);
        }
        lst0 = lst0 * al0 + lacc[0];
        lst1 = lst1 * al1 + lacc[2];

        if (kt + 3 < NTK) load_stage((kt + 3) & 3, kt + 3);
    }

    float inv0 = 1.0f / lst0;
    float inv1 = 1.0f / lst1;
    __half* Og = O + qrow0 * DMODEL + h * DKH;
    #pragma unroll
    for (int nt = 0; nt < 8; nt++) {
        int col = nt * 8 + 2 * lc;
        *(__half2*)(Og + (size_t)(wq + lr) * DMODEL + col) =
            __floats2half2_rn(o[nt][0] * inv0, o[nt][1] * inv0);
        *(__half2*)(Og + (size_t)(wq + lr + 8) * DMODEL + col) =
            __floats2half2_rn(o[nt][2] * inv1, o[nt][3] * inv1);
    }
}

// ---------------- launch ---------------------------------------------------
extern "C" void kernel_launch(void* const* d_in, const int* in_sizes, int n_in,
                              void* d_out, int out_size) {
    const float* X    = (const float*)d_in[0];
    const int*   mask = (const int*)d_in[1];
    const float* Wq   = (const float*)d_in[2];
    const float* Wk   = (const float*)d_in[3];
    const float* Wv   = (const float*)d_in[4];
    const float* Wo   = (const float*)d_in[5];
    float* out = (float*)d_out;

    __half *xh, *qkvh, *aoh, *wth;
    float *mf;
    cudaGetSymbolAddress((void**)&xh,   g_XH);
    cudaGetSymbolAddress((void**)&qkvh, g_QKVH);
    cudaGetSymbolAddress((void**)&aoh,  g_AOH);
    cudaGetSymbolAddress((void**)&wth,  g_WTH);
    cudaGetSymbolAddress((void**)&mf,   g_MF);

    cudaFuncSetAttribute(attn_mma_kernel,
                         cudaFuncAttributeMaxDynamicSharedMemorySize, ATTN_SMEM);
    cudaFuncSetAttribute(tgemm_h_kernel<0>,
                         cudaFuncAttributeMaxDynamicSharedMemorySize, TGEMM_SMEM);
    cudaFuncSetAttribute(tgemm_h_kernel<1>,
                         cudaFuncAttributeMaxDynamicSharedMemorySize, TGEMM_SMEM);

    maskprep_kernel<<<(BATCH*SEQ + 255) / 256, 256>>>(mask, mf);
    xtohalf_kernel<<<MTOT * DMODEL / 4 / 256, 256>>>(X, xh);
    transpose_kernel<<<dim3(32, 32, 4), dim3(32, 8)>>>(Wq, Wk, Wv, Wo, wth);

    tgemm_h_kernel<1><<<dim3(QKVD / 128, MTOT / 128), 256, TGEMM_SMEM>>>(
        xh, wth, qkvh, QKVD, DMODEL, 0.125f * LOG2E);

    attn_mma_kernel<<<dim3(SEQ / 128, NHEAD, BATCH), 256, ATTN_SMEM>>>(qkvh, mf, aoh);

    tgemm_h_kernel<0><<<dim3(DMODEL / 128, MTOT / 128), 256, TGEMM_SMEM>>>(
        aoh, wth + 3 * DMODEL * DMODEL, out, DMODEL, 0, 1.0f);
}